// round 14
// baseline (speedup 1.0000x reference)
#include <cuda_runtime.h>
#include <cuda_fp16.h>
#include <math.h>
#include <stdint.h>

// ---------------- problem constants ----------------
#define XDIM    1024
#define D_STATE 64
#define HEADDIM 128
#define D_INNER 2048
#define NHEADS  16
#define CONVDIM 2176              // D_INNER + 2*64
#define DPROJ   4240              // 2*2048 + 2*64 + 16
#define DPROJP  4352              // padded to 128-multiple for GEMM tiles
#define DT_BASE 4224              // D_INNER + CONVDIM
#define CHUNK   256
#define NBATCH  2
#define SEQLEN  4096
#define NCPB    16
#define NBC     32
#define R_TOT   8192

// ---------------- device scratch ----------------
__device__ __half g_lnh [(size_t)R_TOT * XDIM];
__device__ __half g_Winh[(size_t)DPROJP * XDIM];     // rows >= DPROJ stay zero (.bss)
__device__ __half g_Wouth[(size_t)XDIM * D_INNER];
__device__ __half g_gh  [(size_t)R_TOT * D_INNER];
__device__ __half g_zxh [(size_t)R_TOT * DPROJP];    // fp16 in_proj output
__device__ __half g_xBCh[(size_t)R_TOT * CONVDIM];   // fp16 conv output
__device__ __half g_yh  [(size_t)R_TOT * D_INNER];   // fp16 y
__device__ __half g_Sh  [(size_t)NBC * CHUNK * CHUNK];  // fp16 scores
__device__ __half g_psh [(size_t)NBC * NHEADS * HEADDIM * D_STATE];  // fp16 prev states
__device__ float g_dtraw[(size_t)R_TOT * NHEADS];    // fp32 dt_raw side-channel
__device__ float g_dt  [(size_t)R_TOT * NHEADS];
__device__ float g_cum [(size_t)NBC * NHEADS * CHUNK];
__device__ float g_cdec[(size_t)NBC * NHEADS];
__device__ float g_st  [(size_t)NBC * NHEADS * HEADDIM * D_STATE];

// ---------------- PTX helpers (baseline PTX only) ----------------
__device__ __forceinline__ uint32_t smem_u32(const void* p) {
    uint32_t a;
    asm("{ .reg .u64 t; cvta.to.shared.u64 t, %1; cvt.u32.u64 %0, t; }" : "=r"(a) : "l"(p));
    return a;
}
__device__ __forceinline__ uint32_t pack2(float a, float b) {
    __half2 h = __floats2half2_rn(a, b);
    return *(uint32_t*)&h;
}
__device__ __forceinline__ uint32_t pack2h(__half a, __half b) {
    __half2 h = __halves2half2(a, b);
    return *(uint32_t*)&h;
}
#define CP_ASYNC16(s, g) \
    asm volatile("cp.async.cg.shared.global [%0], [%1], 16;" :: "r"(s), "l"(g))
#define CP_COMMIT() asm volatile("cp.async.commit_group;" ::: "memory")
#define CP_WAIT(n)  asm volatile("cp.async.wait_group %0;" :: "n"(n) : "memory")

__device__ __forceinline__ void ldsm_x4(uint32_t* r, uint32_t addr) {
    asm volatile("ldmatrix.sync.aligned.m8n8.x4.shared.b16 {%0,%1,%2,%3}, [%4];"
        : "=r"(r[0]), "=r"(r[1]), "=r"(r[2]), "=r"(r[3]) : "r"(addr));
}
__device__ __forceinline__ void mma_fp16(float* d, const uint32_t* a, const uint32_t* b) {
    asm volatile("mma.sync.aligned.m16n8k16.row.col.f32.f16.f16.f32 "
        "{%0,%1,%2,%3},{%4,%5,%6,%7},{%8,%9},{%0,%1,%2,%3};"
        : "+f"(d[0]), "+f"(d[1]), "+f"(d[2]), "+f"(d[3])
        : "r"(a[0]), "r"(a[1]), "r"(a[2]), "r"(a[3]), "r"(b[0]), "r"(b[1]));
}

// ================= fp16 tensor-core GEMM =================
#define GBM 128
#define GBN 128
#define GBK 64
#define GSTG 3
#define TB_A (GBM * GBK * 2)
#define TB_B (GBN * GBK * 2)
#define STAGE_B (TB_A + TB_B)
#define GEMM_SMEM (GSTG * STAGE_B)

__device__ __forceinline__ void gemm_load_tile_h(const __half* Ab, const __half* Bb,
                                                 int K, int t, uint32_t sb, int tid) {
    const __half* Ap = Ab + (size_t)t * GBK;
    const __half* Bp = Bb + (size_t)t * GBK;
    #pragma unroll
    for (int j = 0; j < 8; j++) {
        int c = tid + 128 * j;
        int row = c >> 3;
        uint32_t cc = (uint32_t)(c & 7) * 16;
        uint32_t off = (uint32_t)row * 128 + (cc ^ (((uint32_t)row & 7) << 4));
        CP_ASYNC16(sb + off, Ap + (size_t)row * K + (cc >> 1));
    }
    uint32_t sb2 = sb + TB_A;
    #pragma unroll
    for (int j = 0; j < 8; j++) {
        int c = tid + 128 * j;
        int row = c >> 3;
        uint32_t cc = (uint32_t)(c & 7) * 16;
        uint32_t off = (uint32_t)row * 128 + (cc ^ (((uint32_t)row & 7) << 4));
        CP_ASYNC16(sb2 + off, Bp + (size_t)row * K + (cc >> 1));
    }
    CP_COMMIT();
}

#define GEMM_MAIN(acc, A, B, K)                                                     \
    int T = (K) / GBK;                                                              \
    gemm_load_tile_h(A, B, K, 0, sbase, tid);                                       \
    gemm_load_tile_h(A, B, K, 1, sbase + STAGE_B, tid);                             \
    for (int t = 0; t < T; t++) {                                                   \
        CP_WAIT(1);                                                                 \
        __syncthreads();                                                            \
        if (t + 2 < T)                                                              \
            gemm_load_tile_h(A, B, K, t + 2, sbase + ((t + 2) % GSTG) * STAGE_B, tid); \
        uint32_t sa = sbase + (t % GSTG) * STAGE_B;                                 \
        uint32_t sb = sa + TB_A;                                                    \
        _Pragma("unroll")                                                           \
        for (int ks = 0; ks < 4; ks++) {                                            \
            uint32_t afr[4][4];                                                     \
            _Pragma("unroll")                                                       \
            for (int mt = 0; mt < 4; mt++) {                                        \
                uint32_t row = (uint32_t)(a_row + mt * 16);                         \
                uint32_t c = (uint32_t)ks * 32 + a_kb;                              \
                ldsm_x4(afr[mt], sa + row * 128 + (c ^ ((row & 7) << 4)));          \
            }                                                                       \
            uint32_t bfr[4][4];                                                     \
            _Pragma("unroll")                                                       \
            for (int nh = 0; nh < 4; nh++) {                                        \
                uint32_t row = (uint32_t)(b_row + nh * 16);                         \
                uint32_t c = (uint32_t)ks * 32 + b_kb;                              \
                ldsm_x4(bfr[nh], sb + row * 128 + (c ^ ((row & 7) << 4)));          \
            }                                                                       \
            _Pragma("unroll")                                                       \
            for (int mt = 0; mt < 4; mt++)                                          \
                _Pragma("unroll")                                                   \
                for (int nt = 0; nt < 8; nt++)                                      \
                    mma_fp16(acc[mt][nt], afr[mt], &bfr[nt >> 1][(nt & 1) * 2]);    \
        }                                                                           \
    }

// fp32-output GEMM (out_proj)
__global__ __launch_bounds__(128, 2) void gemm_hc(const __half* __restrict__ A,
                                                  const __half* __restrict__ B,
                                                  float* __restrict__ C,
                                                  int K, int ldc) {
    extern __shared__ char sm[];
    uint32_t sbase = smem_u32(sm);
    int tid = threadIdx.x, lane = tid & 31, wid = tid >> 5;
    int wm = (wid & 1) * 64, wn = (wid >> 1) * 64;
    int m0 = blockIdx.y * GBM, n0 = blockIdx.x * GBN;
    const __half* Ab = A + (size_t)m0 * K;
    const __half* Bb = B + (size_t)n0 * K;
    int a_row = wm + (lane & 15);
    uint32_t a_kb = (uint32_t)(lane >> 4) * 16;
    int b_row = wn + (lane & 7) + ((lane & 16) ? 8 : 0);
    uint32_t b_kb = (lane & 8) ? 16u : 0u;

    float acc[4][8][4];
    #pragma unroll
    for (int mt = 0; mt < 4; mt++)
        #pragma unroll
        for (int nt = 0; nt < 8; nt++)
            #pragma unroll
            for (int q = 0; q < 4; q++) acc[mt][nt][q] = 0.f;

    GEMM_MAIN(acc, Ab, Bb, K)

    int g = lane >> 2, tg = lane & 3;
    #pragma unroll
    for (int mt = 0; mt < 4; mt++) {
        int rowa = m0 + wm + mt * 16 + g;
        #pragma unroll
        for (int nt = 0; nt < 8; nt++) {
            int col = n0 + wn + nt * 8 + tg * 2;
            *(float2*)(C + (size_t)rowa * ldc + col) =
                make_float2(acc[mt][nt][0], acc[mt][nt][1]);
            *(float2*)(C + (size_t)(rowa + 8) * ldc + col) =
                make_float2(acc[mt][nt][2], acc[mt][nt][3]);
        }
    }
}

// fp16-output GEMM (in_proj) with fp32 dt side-channel
__global__ __launch_bounds__(128, 2) void gemm_hc_h(const __half* __restrict__ A,
                                                    const __half* __restrict__ B,
                                                    __half* __restrict__ C,
                                                    int K, int ldc) {
    extern __shared__ char sm[];
    uint32_t sbase = smem_u32(sm);
    int tid = threadIdx.x, lane = tid & 31, wid = tid >> 5;
    int wm = (wid & 1) * 64, wn = (wid >> 1) * 64;
    int m0 = blockIdx.y * GBM, n0 = blockIdx.x * GBN;
    const __half* Ab = A + (size_t)m0 * K;
    const __half* Bb = B + (size_t)n0 * K;
    int a_row = wm + (lane & 15);
    uint32_t a_kb = (uint32_t)(lane >> 4) * 16;
    int b_row = wn + (lane & 7) + ((lane & 16) ? 8 : 0);
    uint32_t b_kb = (lane & 8) ? 16u : 0u;

    float acc[4][8][4];
    #pragma unroll
    for (int mt = 0; mt < 4; mt++)
        #pragma unroll
        for (int nt = 0; nt < 8; nt++)
            #pragma unroll
            for (int q = 0; q < 4; q++) acc[mt][nt][q] = 0.f;

    GEMM_MAIN(acc, Ab, Bb, K)

    int g = lane >> 2, tg = lane & 3;
    #pragma unroll
    for (int mt = 0; mt < 4; mt++) {
        int rowa = m0 + wm + mt * 16 + g;
        #pragma unroll
        for (int nt = 0; nt < 8; nt++) {
            int col = n0 + wn + nt * 8 + tg * 2;
            *(uint32_t*)(C + (size_t)rowa * ldc + col) =
                pack2(acc[mt][nt][0], acc[mt][nt][1]);
            *(uint32_t*)(C + (size_t)(rowa + 8) * ldc + col) =
                pack2(acc[mt][nt][2], acc[mt][nt][3]);
            if (col >= DT_BASE && col < DPROJ) {
                int d = col - DT_BASE;
                g_dtraw[(size_t)rowa * NHEADS + d]     = acc[mt][nt][0];
                g_dtraw[(size_t)rowa * NHEADS + d + 1] = acc[mt][nt][1];
                g_dtraw[(size_t)(rowa + 8) * NHEADS + d]     = acc[mt][nt][2];
                g_dtraw[(size_t)(rowa + 8) * NHEADS + d + 1] = acc[mt][nt][3];
            }
        }
    }
}

// ---------------- reductions ----------------
__device__ __forceinline__ float blockReduceSum256(float v) {
    __shared__ float red[8];
    __shared__ float tot;
    int lane = threadIdx.x & 31, wid = threadIdx.x >> 5;
    #pragma unroll
    for (int o = 16; o; o >>= 1) v += __shfl_down_sync(0xffffffffu, v, o);
    if (lane == 0) red[wid] = v;
    __syncthreads();
    if (wid == 0) {
        float w = (lane < 8) ? red[lane] : 0.f;
        #pragma unroll
        for (int o = 4; o; o >>= 1) w += __shfl_down_sync(0xffffffffu, w, o);
        if (lane == 0) tot = w;
    }
    __syncthreads();
    return tot;
}

// ============ merged prologue: layernorm rows + l2norm of both weights ============
__global__ __launch_bounds__(256) void k_prolog(const float* __restrict__ u,
                                                const float* __restrict__ xnw,
                                                const float* __restrict__ xnb,
                                                const float* __restrict__ Win,
                                                const float* __restrict__ Wout) {
    int bid = blockIdx.x;
    if (bid < R_TOT) {
        // layernorm row
        const float* ur = u + (size_t)bid * XDIM;
        float v[4]; float s = 0.f, s2 = 0.f;
        #pragma unroll
        for (int k = 0; k < 4; k++) {
            v[k] = ur[threadIdx.x + 256 * k];
            s += v[k]; s2 += v[k] * v[k];
        }
        float sum = blockReduceSum256(s);
        float sumsq = blockReduceSum256(s2);
        float mu = sum * (1.f / XDIM);
        float var = sumsq * (1.f / XDIM) - mu * mu;
        float inv = rsqrtf(var + 1e-5f);
        #pragma unroll
        for (int k = 0; k < 4; k++) {
            int d = threadIdx.x + 256 * k;
            g_lnh[(size_t)bid * XDIM + d] = __float2half_rn((v[k] - mu) * inv * xnw[d] + xnb[d]);
        }
    } else if (bid < R_TOT + DPROJ) {
        // in_proj weight row (K = XDIM), fold DIM^-0.5
        int r = bid - R_TOT;
        const float* wr = Win + (size_t)r * XDIM;
        float s2 = 0.f;
        for (int i = threadIdx.x; i < XDIM; i += 256) { float v = wr[i]; s2 += v * v; }
        float totv = blockReduceSum256(s2);
        float sc = 0.03125f / fmaxf(sqrtf(totv), 1e-6f);
        for (int i = threadIdx.x; i < XDIM; i += 256)
            g_Winh[(size_t)r * XDIM + i] = __float2half_rn(wr[i] * sc);
    } else {
        // out_proj weight row (K = D_INNER)
        int r = bid - R_TOT - DPROJ;
        const float* wr = Wout + (size_t)r * D_INNER;
        float s2 = 0.f;
        for (int i = threadIdx.x; i < D_INNER; i += 256) { float v = wr[i]; s2 += v * v; }
        float totv = blockReduceSum256(s2);
        float sc = 1.0f / fmaxf(sqrtf(totv), 1e-6f);
        for (int i = threadIdx.x; i < D_INNER; i += 256)
            g_Wouth[(size_t)r * D_INNER + i] = __float2half_rn(wr[i] * sc);
    }
}

// ============ merged SSD stage-1: scores (96 blocks) + states (512 blocks) ============
__global__ __launch_bounds__(256, 2) void k_ssd1() {
    __shared__ __align__(16) __half As[128 * 64];
    __shared__ __align__(16) __half Bs[128 * 64];
    __shared__ float wsh[256];
    int tid = threadIdx.x, lane = tid & 31, wid = tid >> 5;
    uint32_t as_base = smem_u32(As);
    uint32_t bs_base = smem_u32(Bs);
    int bid = blockIdx.x;

    if (bid < NBC * 3) {
        // ---- scores: S tile = C @ B^T, K=64 ----
        int bc = bid / 3;
        int tile = bid - bc * 3;
        int i0 = (tile != 0) ? 128 : 0;
        int j0 = (tile == 2) ? 128 : 0;
        int row0 = bc * CHUNK;
        const __half* Cb = g_xBCh + (size_t)(row0 + i0) * CONVDIM + D_INNER + D_STATE;
        const __half* Bb = g_xBCh + (size_t)(row0 + j0) * CONVDIM + D_INNER;
        #pragma unroll
        for (int j = 0; j < 4; j++) {
            int c = tid + 256 * j;
            int row = c >> 3;
            uint32_t cc = (uint32_t)(c & 7) * 16;
            uint32_t off = (uint32_t)row * 128 + (cc ^ (((uint32_t)row & 7) << 4));
            CP_ASYNC16(as_base + off, Cb + (size_t)row * CONVDIM + (cc >> 1));
            CP_ASYNC16(bs_base + off, Bb + (size_t)row * CONVDIM + (cc >> 1));
        }
        CP_COMMIT();
        CP_WAIT(0);
        __syncthreads();

        int wm = (wid & 3) * 32;
        int wn = (wid >> 2) * 64;
        int a_row = wm + (lane & 15);
        uint32_t a_kb = (uint32_t)(lane >> 4) * 16;
        int b_row = wn + (lane & 7) + ((lane & 16) ? 8 : 0);
        uint32_t b_kb = (lane & 8) ? 16u : 0u;

        float acc[2][8][4];
        #pragma unroll
        for (int mt = 0; mt < 2; mt++)
            #pragma unroll
            for (int nt = 0; nt < 8; nt++)
                #pragma unroll
                for (int q = 0; q < 4; q++) acc[mt][nt][q] = 0.f;

        #pragma unroll
        for (int ks = 0; ks < 4; ks++) {
            uint32_t afr[2][4];
            #pragma unroll
            for (int mt = 0; mt < 2; mt++) {
                uint32_t row = (uint32_t)(a_row + mt * 16);
                uint32_t c = (uint32_t)ks * 32 + a_kb;
                ldsm_x4(afr[mt], as_base + row * 128 + (c ^ ((row & 7) << 4)));
            }
            uint32_t bfr[4][4];
            #pragma unroll
            for (int nh = 0; nh < 4; nh++) {
                uint32_t row = (uint32_t)(b_row + nh * 16);
                uint32_t c = (uint32_t)ks * 32 + b_kb;
                ldsm_x4(bfr[nh], bs_base + row * 128 + (c ^ ((row & 7) << 4)));
            }
            #pragma unroll
            for (int mt = 0; mt < 2; mt++)
                #pragma unroll
                for (int nt = 0; nt < 8; nt++)
                    mma_fp16(acc[mt][nt], afr[mt], &bfr[nt >> 1][(nt & 1) * 2]);
        }

        int g = lane >> 2, tg = lane & 3;
        #pragma unroll
        for (int mt = 0; mt < 2; mt++) {
            int irow = i0 + wm + mt * 16 + g;
            #pragma unroll
            for (int nt = 0; nt < 8; nt++) {
                int col = j0 + wn + nt * 8 + tg * 2;
                *(uint32_t*)(g_Sh + ((size_t)bc * CHUNK + irow) * CHUNK + col) =
                    pack2(acc[mt][nt][0], acc[mt][nt][1]);
                *(uint32_t*)(g_Sh + ((size_t)bc * CHUNK + irow + 8) * CHUNK + col) =
                    pack2(acc[mt][nt][2], acc[mt][nt][3]);
            }
        }
    } else {
        // ---- states: states[p][n] = sum_t (x[t][p]*w_t) * B[t][n] ----
        int idx = bid - NBC * 3;
        int bc = idx >> 4, h = idx & 15;
        int row0 = bc * CHUNK;
        int cb = (bc * NHEADS + h) * CHUNK;

        float cum_last = g_cum[cb + 255];
        wsh[tid] = g_dt[(size_t)(row0 + tid) * NHEADS + h] *
                   __expf(cum_last - g_cum[cb + tid]);

        int wm = (wid & 3) * 32;
        int wn = (wid >> 2) * 32;
        int a_row = wm + (lane & 15);
        uint32_t a_kb = (uint32_t)(lane >> 4) * 16;
        int b_row = wn + (lane & 7) + ((lane & 16) ? 8 : 0);
        uint32_t b_kb = (lane & 8) ? 16u : 0u;

        float acc[2][4][4];
        #pragma unroll
        for (int mt = 0; mt < 2; mt++)
            #pragma unroll
            for (int nt = 0; nt < 4; nt++)
                #pragma unroll
                for (int q = 0; q < 4; q++) acc[mt][nt][q] = 0.f;

        for (int kt = 0; kt < 4; kt++) {
            int t0 = kt * 64;
            __syncthreads();
            #pragma unroll
            for (int jp = 0; jp < 4; jp++) {
                int pair = wid + 8 * jp;
                int t = t0 + 2 * pair;
                const __half* x0 = g_xBCh + (size_t)(row0 + t) * CONVDIM + h * HEADDIM;
                const __half* x1 = x0 + CONVDIM;
                float w0 = wsh[t], w1 = wsh[t + 1];
                #pragma unroll
                for (int r = 0; r < 4; r++) {
                    int p = lane + 32 * r;
                    uint32_t cbyte = (uint32_t)pair * 4;
                    uint32_t off = (uint32_t)p * 128 + (cbyte ^ (((uint32_t)p & 7) << 4));
                    *(uint32_t*)((char*)As + off) =
                        pack2(__half2float(x0[p]) * w0, __half2float(x1[p]) * w1);
                }
            }
            #pragma unroll
            for (int q = 0; q < 8; q++) {
                int idx2 = tid + 256 * q;
                int n = idx2 >> 5, pair = idx2 & 31;
                int t = t0 + 2 * pair;
                const __half* b0 = g_xBCh + (size_t)(row0 + t) * CONVDIM + D_INNER;
                uint32_t cbyte = (uint32_t)pair * 4;
                uint32_t off = (uint32_t)n * 128 + (cbyte ^ (((uint32_t)n & 7) << 4));
                *(uint32_t*)((char*)Bs + off) = pack2h(b0[n], b0[CONVDIM + n]);
            }
            __syncthreads();
            #pragma unroll
            for (int ks = 0; ks < 4; ks++) {
                uint32_t afr[2][4];
                #pragma unroll
                for (int mt = 0; mt < 2; mt++) {
                    uint32_t row = (uint32_t)(a_row + mt * 16);
                    uint32_t c = (uint32_t)ks * 32 + a_kb;
                    ldsm_x4(afr[mt], as_base + row * 128 + (c ^ ((row & 7) << 4)));
                }
                uint32_t bfr[2][4];
                #pragma unroll
                for (int nh = 0; nh < 2; nh++) {
                    uint32_t row = (uint32_t)(b_row + nh * 16);
                    uint32_t c = (uint32_t)ks * 32 + b_kb;
                    ldsm_x4(bfr[nh], bs_base + row * 128 + (c ^ ((row & 7) << 4)));
                }
                #pragma unroll
                for (int mt = 0; mt < 2; mt++)
                    #pragma unroll
                    for (int nt = 0; nt < 4; nt++)
                        mma_fp16(acc[mt][nt], afr[mt], &bfr[nt >> 1][(nt & 1) * 2]);
            }
        }

        size_t base = (size_t)(bc * NHEADS + h) * HEADDIM * D_STATE;
        int g = lane >> 2, tg = lane & 3;
        #pragma unroll
        for (int mt = 0; mt < 2; mt++) {
            int prow = wm + mt * 16 + g;
            #pragma unroll
            for (int nt = 0; nt < 4; nt++) {
                int col = wn + nt * 8 + tg * 2;
                *(float2*)(g_st + base + (size_t)prow * D_STATE + col) =
                    make_float2(acc[mt][nt][0], acc[mt][nt][1]);
                *(float2*)(g_st + base + (size_t)(prow + 8) * D_STATE + col) =
                    make_float2(acc[mt][nt][2], acc[mt][nt][3]);
            }
        }
    }
}

// ============ fused SSD y-kernel (fp16 fragments, fp32 accumulate, fp16 y out) ============
__global__ __launch_bounds__(256, 2) void k_yfused() {
    __shared__ __align__(16) __half As[128 * 64];
    __shared__ __align__(16) __half Bs[128 * 64];
    __shared__ float gj_all[256];
    __shared__ float cas[8];
    int bc = blockIdx.x, h = blockIdx.y, ih = blockIdx.z;
    int i_base = ih * 128;
    int row0 = bc * CHUNK;
    int cb = (bc * NHEADS + h) * CHUNK;
    size_t psb = (size_t)(bc * NHEADS + h) * HEADDIM * D_STATE;

    int tid = threadIdx.x, lane = tid & 31, wid = tid >> 5;
    int wm = (wid & 3) * 32;
    int wn = (wid >> 2) * 64;

    int si = tid >> 1;
    int sj = (tid & 1) * 32;
    int gi = i_base + si;
    float ci = g_cum[cb + gi];
    float ei = __expf(ci);

    uint32_t as_base = smem_u32(As);
    uint32_t bs_base = smem_u32(Bs);

    int a_row = wm + (lane & 15);
    uint32_t a_kb = (uint32_t)(lane >> 4) * 16;
    int b_row = wn + (lane & 7) + ((lane & 16) ? 8 : 0);
    uint32_t b_kb = (lane & 8) ? 16u : 0u;

    int natt64 = (ih + 1) * 2;
    int nattj = natt64 * 64;

    if (tid < nattj) {
        int j = tid;
        float ca = g_cum[cb + (j & ~31) + 31];
        gj_all[j] = __expf(ca - g_cum[cb + j]) *
                    g_dt[(size_t)(row0 + j) * NHEADS + h];
    }
    if (tid < natt64 * 2) cas[tid] = g_cum[cb + tid * 32 + 31];

    float acc[2][8][4];
    #pragma unroll
    for (int mt = 0; mt < 2; mt++)
        #pragma unroll
        for (int nt = 0; nt < 8; nt++)
            #pragma unroll
            for (int q = 0; q < 4; q++) acc[mt][nt][q] = 0.f;

    int ntiles = natt64 + 1;
    for (int kt = 0; kt < ntiles; kt++) {
        __syncthreads();
        if (kt < natt64) {
            int j0 = kt * 64;
            int jb = j0 + sj;
            if (gi >= jb + 31) {
                float fi = __expf(ci - cas[jb >> 5]);
                const __half* Srow = g_Sh + ((size_t)bc * CHUNK + gi) * CHUNK + jb;
                const float* gjp = gj_all + jb;
                #pragma unroll
                for (int q = 0; q < 4; q++) {
                    uint4 sv = *(const uint4*)(Srow + q * 8);
                    float2 f0 = __half22float2(*(__half2*)&sv.x);
                    float2 f1 = __half22float2(*(__half2*)&sv.y);
                    float2 f2 = __half22float2(*(__half2*)&sv.z);
                    float2 f3 = __half22float2(*(__half2*)&sv.w);
                    uint4 u;
                    u.x = pack2(f0.x * fi * gjp[q*8+0], f0.y * fi * gjp[q*8+1]);
                    u.y = pack2(f1.x * fi * gjp[q*8+2], f1.y * fi * gjp[q*8+3]);
                    u.z = pack2(f2.x * fi * gjp[q*8+4], f2.y * fi * gjp[q*8+5]);
                    u.w = pack2(f3.x * fi * gjp[q*8+6], f3.y * fi * gjp[q*8+7]);
                    uint32_t cbyte = (uint32_t)(sj * 2 + q * 16);
                    uint32_t off = (uint32_t)si * 128 + (cbyte ^ (((uint32_t)si & 7) << 4));
                    *(uint4*)((char*)As + off) = u;
                }
            } else if (gi >= jb) {
                #pragma unroll
                for (int q = 0; q < 4; q++) {
                    float v[8];
                    #pragma unroll
                    for (int r = 0; r < 8; r++) {
                        int j = jb + q * 8 + r;
                        float a = 0.f;
                        if (j <= gi)
                            a = __half2float(g_Sh[((size_t)bc * CHUNK + gi) * CHUNK + j]) *
                                __expf(ci - g_cum[cb + j]) *
                                g_dt[(size_t)(row0 + j) * NHEADS + h];
                        v[r] = a;
                    }
                    uint4 u;
                    u.x = pack2(v[0], v[1]); u.y = pack2(v[2], v[3]);
                    u.z = pack2(v[4], v[5]); u.w = pack2(v[6], v[7]);
                    uint32_t cbyte = (uint32_t)(sj * 2 + q * 16);
                    uint32_t off = (uint32_t)si * 128 + (cbyte ^ (((uint32_t)si & 7) << 4));
                    *(uint4*)((char*)As + off) = u;
                }
            } else {
                #pragma unroll
                for (int q = 0; q < 4; q++) {
                    uint32_t cbyte = (uint32_t)(sj * 2 + q * 16);
                    uint32_t off = (uint32_t)si * 128 + (cbyte ^ (((uint32_t)si & 7) << 4));
                    *(uint4*)((char*)As + off) = make_uint4(0, 0, 0, 0);
                }
            }
            #pragma unroll
            for (int jp = 0; jp < 4; jp++) {
                int pair = wid + 8 * jp;
                int j = j0 + 2 * pair;
                const __half* x0 = g_xBCh + (size_t)(row0 + j) * CONVDIM + h * HEADDIM;
                const __half* x1 = x0 + CONVDIM;
                #pragma unroll
                for (int r = 0; r < 4; r++) {
                    int p = lane + 32 * r;
                    uint32_t cbyte = (uint32_t)pair * 4;
                    uint32_t off = (uint32_t)p * 128 + (cbyte ^ (((uint32_t)p & 7) << 4));
                    *(uint32_t*)((char*)Bs + off) = pack2h(x0[p], x1[p]);
                }
            }
        } else {
            const __half2* crow = (const __half2*)(g_xBCh + (size_t)(row0 + gi) * CONVDIM
                                                   + D_INNER + D_STATE + sj);
            #pragma unroll
            for (int q = 0; q < 4; q++) {
                uint4 hv = *(const uint4*)(crow + q * 4);
                float2 f0 = __half22float2(*(__half2*)&hv.x);
                float2 f1 = __half22float2(*(__half2*)&hv.y);
                float2 f2 = __half22float2(*(__half2*)&hv.z);
                float2 f3 = __half22float2(*(__half2*)&hv.w);
                uint4 u;
                u.x = pack2(f0.x * ei, f0.y * ei);
                u.y = pack2(f1.x * ei, f1.y * ei);
                u.z = pack2(f2.x * ei, f2.y * ei);
                u.w = pack2(f3.x * ei, f3.y * ei);
                uint32_t cbyte = (uint32_t)(sj * 2 + q * 16);
                uint32_t off = (uint32_t)si * 128 + (cbyte ^ (((uint32_t)si & 7) << 4));
                *(uint4*)((char*)As + off) = u;
            }
            int pr = tid >> 1;
            int nc = (tid & 1) * 32;
            const __half* prow = g_psh + psb + (size_t)pr * D_STATE + nc;
            #pragma unroll
            for (int q = 0; q < 2; q++) {
                uint4 u = *(const uint4*)(prow + q * 16);
                uint32_t off = (uint32_t)pr * 128 +
                    (((uint32_t)(nc * 2 + q * 32)) ^ (((uint32_t)pr & 7) << 4));
                *(uint4*)((char*)Bs + off) = u;
                uint4 u2 = *(const uint4*)(prow + q * 16 + 8);
                uint32_t off2 = (uint32_t)pr * 128 +
                    (((uint32_t)(nc * 2 + q * 32 + 16)) ^ (((uint32_t)pr & 7) << 4));
                *(uint4*)((char*)Bs + off2) = u2;
            }
        }
        __syncthreads();
        #pragma unroll
        for (int ks = 0; ks < 4; ks++) {
            uint32_t afr[2][4];
            #pragma unroll
            for (int mt = 0; mt < 2; mt++) {
                uint32_t row = (uint32_t)(a_row + mt * 16);
                uint32_t c = (uint32_t)ks * 32 + a_kb;
                ldsm_x4(afr[mt], as_base + row * 128 + (c ^ ((row & 7) << 4)));
            }
            uint32_t bfr[4][4];
            #pragma unroll
            for (int nh = 0; nh < 4; nh++) {
                uint32_t row = (uint32_t)(b_row + nh * 16);
                uint32_t c = (uint32_t)ks * 32 + b_kb;
                ldsm_x4(bfr[nh], bs_base + row * 128 + (c ^ ((row & 7) << 4)));
            }
            #pragma unroll
            for (int mt = 0; mt < 2; mt++)
                #pragma unroll
                for (int nt = 0; nt < 8; nt++)
                    mma_fp16(acc[mt][nt], afr[mt], &bfr[nt >> 1][(nt & 1) * 2]);
        }
    }

    int g = lane >> 2, tg = lane & 3;
    #pragma unroll
    for (int mt = 0; mt < 2; mt++) {
        int orow = row0 + i_base + wm + mt * 16 + g;
        #pragma unroll
        for (int nt = 0; nt < 8; nt++) {
            int col = h * HEADDIM + wn + nt * 8 + tg * 2;
            *(uint32_t*)(g_yh + (size_t)orow * D_INNER + col) =
                pack2(acc[mt][nt][0], acc[mt][nt][1]);
            *(uint32_t*)(g_yh + (size_t)(orow + 8) * D_INNER + col) =
                pack2(acc[mt][nt][2], acc[mt][nt][3]);
        }
    }
}

// ---------------- K4: depthwise causal conv + bias + silu ----------------
__global__ __launch_bounds__(128) void k_conv(const float* __restrict__ cw,
                                              const float* __restrict__ cb) {
    int ch = blockIdx.x * 128 + threadIdx.x;
    if (ch >= CONVDIM) return;
    int row0 = blockIdx.y * 8;
    int l0 = row0 & (SEQLEN - 1);
    float w0 = cw[ch * 4 + 0], w1 = cw[ch * 4 + 1];
    float w2 = cw[ch * 4 + 2], w3 = cw[ch * 4 + 3];
    float bias = cb[ch];
    float v[11];
    #pragma unroll
    for (int k = 0; k < 11; k++) {
        int l = l0 - 3 + k;
        v[k] = (l >= 0)
            ? __half2float(g_zxh[(size_t)(row0 - 3 + k) * DPROJP + D_INNER + ch]) : 0.f;
    }
    #pragma unroll
    for (int r = 0; r < 8; r++) {
        float acc = bias + w0 * v[r] + w1 * v[r + 1] + w2 * v[r + 2] + w3 * v[r + 3];
        float s = acc / (1.f + __expf(-acc));
        g_xBCh[(size_t)(row0 + r) * CONVDIM + ch] = __float2half_rn(s);
    }
}

// ---------------- K5: dt softplus + per-chunk cumulative dA ----------------
__global__ __launch_bounds__(256) void k_dtcum(const float* __restrict__ dt_bias,
                                               const float* __restrict__ A_log) {
    int bch = blockIdx.x;
    int h = bch & 15, bc = bch >> 4;
    int t = threadIdx.x;
    int row = bc * CHUNK + t;
    float x = g_dtraw[(size_t)row * NHEADS + h] + dt_bias[h];
    float dtv = (x > 20.f) ? x : log1pf(expf(x));
    g_dt[(size_t)row * NHEADS + h] = dtv;
    float dA = dtv * (-expf(A_log[h]));
    __shared__ float s[256];
    s[t] = dA;
    __syncthreads();
    #pragma unroll
    for (int off = 1; off < 256; off <<= 1) {
        float pv = (t >= off) ? s[t - off] : 0.f;
        __syncthreads();
        s[t] += pv;
        __syncthreads();
    }
    g_cum[(size_t)bch * CHUNK + t] = s[t];
    if (t == 255) g_cdec[bch] = __expf(s[255]);
}

// ---------------- K8: inter-chunk scan (fp32 carry, fp16 ps out) ----------------
__global__ __launch_bounds__(256) void k_scan() {
    int b = blockIdx.x, h = blockIdx.y, z = blockIdx.z;
    int tid = threadIdx.x;
    int e0 = z * 1024 + tid * 4;
    float4 carry = make_float4(0.f, 0.f, 0.f, 0.f);
    for (int c = 0; c < NCPB; c++) {
        int bch = (b * NCPB + c) * NHEADS + h;
        float dec = g_cdec[bch];
        size_t base = (size_t)bch * HEADDIM * D_STATE + e0;
        uint2 pk;
        pk.x = pack2(carry.x, carry.y);
        pk.y = pack2(carry.z, carry.w);
        *(uint2*)(g_psh + base) = pk;
        float4 st = *(const float4*)(g_st + base);
        carry.x = carry.x * dec + st.x;
        carry.y = carry.y * dec + st.y;
        carry.z = carry.z * dec + st.z;
        carry.w = carry.w * dec + st.w;
    }
}

// ---------------- K10: y += D*x, gate, RMS norm ----------------
__global__ __launch_bounds__(256) void k_gate(const float* __restrict__ Dp,
                                              const float* __restrict__ rms_w) {
    int row = blockIdx.x;
    int tid = threadIdx.x;
    float gg[8];
    float s2 = 0.f;
    #pragma unroll
    for (int k = 0; k < 8; k++) {
        int d = tid + 256 * k;
        float xv = __half2float(g_xBCh[(size_t)row * CONVDIM + d]);
        float yv = __half2float(g_yh[(size_t)row * D_INNER + d]);
        float v = yv + Dp[d >> 7] * xv;
        float z = __half2float(g_zxh[(size_t)row * DPROJP + d]);
        float sil = z / (1.f + __expf(-z));
        float g = v * sil;
        gg[k] = g;
        s2 += g * g;
    }
    float tot = blockReduceSum256(s2);
    float sc = rsqrtf(tot * (1.f / D_INNER) + 1e-5f);
    #pragma unroll
    for (int k = 0; k < 8; k++) {
        int d = tid + 256 * k;
        g_gh[(size_t)row * D_INNER + d] = __float2half_rn(gg[k] * sc * rms_w[d]);
    }
}

// ---------------- host launcher ----------------
extern "C" void kernel_launch(void* const* d_in, const int* in_sizes, int n_in,
                              void* d_out, int out_size) {
    const float* u          = (const float*)d_in[0];
    const float* in_proj_w  = (const float*)d_in[1];
    const float* conv_w     = (const float*)d_in[2];
    const float* conv_b     = (const float*)d_in[3];
    const float* dt_bias    = (const float*)d_in[4];
    const float* A_log      = (const float*)d_in[5];
    const float* Dp         = (const float*)d_in[6];
    const float* xnw        = (const float*)d_in[7];
    const float* xnb        = (const float*)d_in[8];
    const float* rms_w      = (const float*)d_in[9];
    const float* out_proj_w = (const float*)d_in[10];
    float* out = (float*)d_out;

    __half *pWinH, *pWoutH, *pLnH, *pGH, *pZxH;
    cudaGetSymbolAddress((void**)&pWinH,  g_Winh);
    cudaGetSymbolAddress((void**)&pWoutH, g_Wouth);
    cudaGetSymbolAddress((void**)&pLnH,   g_lnh);
    cudaGetSymbolAddress((void**)&pGH,    g_gh);
    cudaGetSymbolAddress((void**)&pZxH,   g_zxh);

    static int smem_set = 0;
    if (!smem_set) {
        cudaFuncSetAttribute(gemm_hc, cudaFuncAttributeMaxDynamicSharedMemorySize, GEMM_SMEM);
        cudaFuncSetAttribute(gemm_hc_h, cudaFuncAttributeMaxDynamicSharedMemorySize, GEMM_SMEM);
        smem_set = 1;
    }

    // merged prologue: layernorm + both weight l2-norms
    k_prolog<<<R_TOT + DPROJ + XDIM, 256>>>(u, xnw, xnb, in_proj_w, out_proj_w);

    gemm_hc_h<<<dim3(DPROJP / GBN, R_TOT / GBM), 128, GEMM_SMEM>>>(pLnH, pWinH, pZxH, XDIM, DPROJP);

    k_conv<<<dim3((CONVDIM + 127) / 128, R_TOT / 8), 128>>>(conv_w, conv_b);
    k_dtcum<<<NBC * NHEADS, 256>>>(dt_bias, A_log);

    // merged SSD stage-1: scores + states
    k_ssd1<<<NBC * 3 + NBC * NHEADS, 256>>>();
    k_scan<<<dim3(NBATCH, NHEADS, 8), 256>>>();
    k_yfused<<<dim3(NBC, NHEADS, 2), 256>>>();

    k_gate<<<R_TOT, 256>>>(Dp, rms_w);

    gemm_hc<<<dim3(XDIM / GBN, R_TOT / GBM), 128, GEMM_SMEM>>>(pGH, pWoutH, out, D_INNER, XDIM);
}

// round 15
// speedup vs baseline: 1.0055x; 1.0055x over previous
#include <cuda_runtime.h>
#include <cuda_fp16.h>
#include <math.h>
#include <stdint.h>

// ---------------- problem constants ----------------
#define XDIM    1024
#define D_STATE 64
#define HEADDIM 128
#define D_INNER 2048
#define NHEADS  16
#define CONVDIM 2176              // D_INNER + 2*64
#define DPROJ   4240              // 2*2048 + 2*64 + 16
#define DPROJP  4352              // padded to 128-multiple for GEMM tiles
#define DT_BASE 4224              // D_INNER + CONVDIM
#define CHUNK   256
#define NBATCH  2
#define SEQLEN  4096
#define NCPB    16
#define NBC     32
#define R_TOT   8192

// ---------------- device scratch ----------------
__device__ __half g_lnh [(size_t)R_TOT * XDIM];
__device__ __half g_Winh[(size_t)DPROJP * XDIM];     // rows >= DPROJ stay zero (.bss)
__device__ __half g_Wouth[(size_t)XDIM * D_INNER];
__device__ __half g_gh  [(size_t)R_TOT * D_INNER];
__device__ __half g_zxh [(size_t)R_TOT * DPROJP];    // fp16 in_proj output
__device__ __half g_xBCh[(size_t)R_TOT * CONVDIM];   // fp16 conv output
__device__ __half g_yh  [(size_t)R_TOT * D_INNER];   // fp16 y
__device__ __half g_Sh  [(size_t)NBC * CHUNK * CHUNK];  // fp16 scores
__device__ __half g_psh [(size_t)NBC * NHEADS * HEADDIM * D_STATE];  // fp16 prev states
__device__ float g_dtraw[(size_t)R_TOT * NHEADS];    // fp32 dt_raw side-channel
__device__ float g_dt  [(size_t)R_TOT * NHEADS];
__device__ float g_cum [(size_t)NBC * NHEADS * CHUNK];
__device__ float g_cdec[(size_t)NBC * NHEADS];
__device__ float g_st  [(size_t)NBC * NHEADS * HEADDIM * D_STATE];

// ---------------- PTX helpers (baseline PTX only) ----------------
__device__ __forceinline__ uint32_t smem_u32(const void* p) {
    uint32_t a;
    asm("{ .reg .u64 t; cvta.to.shared.u64 t, %1; cvt.u32.u64 %0, t; }" : "=r"(a) : "l"(p));
    return a;
}
__device__ __forceinline__ uint32_t pack2(float a, float b) {
    __half2 h = __floats2half2_rn(a, b);
    return *(uint32_t*)&h;
}
__device__ __forceinline__ uint32_t pack2h(__half a, __half b) {
    __half2 h = __halves2half2(a, b);
    return *(uint32_t*)&h;
}
#define CP_ASYNC16(s, g) \
    asm volatile("cp.async.cg.shared.global [%0], [%1], 16;" :: "r"(s), "l"(g))
#define CP_COMMIT() asm volatile("cp.async.commit_group;" ::: "memory")
#define CP_WAIT(n)  asm volatile("cp.async.wait_group %0;" :: "n"(n) : "memory")

__device__ __forceinline__ void ldsm_x4(uint32_t* r, uint32_t addr) {
    asm volatile("ldmatrix.sync.aligned.m8n8.x4.shared.b16 {%0,%1,%2,%3}, [%4];"
        : "=r"(r[0]), "=r"(r[1]), "=r"(r[2]), "=r"(r[3]) : "r"(addr));
}
__device__ __forceinline__ void mma_fp16(float* d, const uint32_t* a, const uint32_t* b) {
    asm volatile("mma.sync.aligned.m16n8k16.row.col.f32.f16.f16.f32 "
        "{%0,%1,%2,%3},{%4,%5,%6,%7},{%8,%9},{%0,%1,%2,%3};"
        : "+f"(d[0]), "+f"(d[1]), "+f"(d[2]), "+f"(d[3])
        : "r"(a[0]), "r"(a[1]), "r"(a[2]), "r"(a[3]), "r"(b[0]), "r"(b[1]));
}

// ================= fp16 tensor-core GEMM =================
#define GBM 128
#define GBN 128
#define GBK 64
#define GSTG 3
#define TB_A (GBM * GBK * 2)
#define TB_B (GBN * GBK * 2)
#define STAGE_B (TB_A + TB_B)
#define GEMM_SMEM (GSTG * STAGE_B)

__device__ __forceinline__ void gemm_load_tile_h(const __half* Ab, const __half* Bb,
                                                 int K, int t, uint32_t sb, int tid) {
    const __half* Ap = Ab + (size_t)t * GBK;
    const __half* Bp = Bb + (size_t)t * GBK;
    #pragma unroll
    for (int j = 0; j < 8; j++) {
        int c = tid + 128 * j;
        int row = c >> 3;
        uint32_t cc = (uint32_t)(c & 7) * 16;
        uint32_t off = (uint32_t)row * 128 + (cc ^ (((uint32_t)row & 7) << 4));
        CP_ASYNC16(sb + off, Ap + (size_t)row * K + (cc >> 1));
    }
    uint32_t sb2 = sb + TB_A;
    #pragma unroll
    for (int j = 0; j < 8; j++) {
        int c = tid + 128 * j;
        int row = c >> 3;
        uint32_t cc = (uint32_t)(c & 7) * 16;
        uint32_t off = (uint32_t)row * 128 + (cc ^ (((uint32_t)row & 7) << 4));
        CP_ASYNC16(sb2 + off, Bp + (size_t)row * K + (cc >> 1));
    }
    CP_COMMIT();
}

#define GEMM_MAIN(acc, A, B, K)                                                     \
    int T = (K) / GBK;                                                              \
    gemm_load_tile_h(A, B, K, 0, sbase, tid);                                       \
    gemm_load_tile_h(A, B, K, 1, sbase + STAGE_B, tid);                             \
    for (int t = 0; t < T; t++) {                                                   \
        CP_WAIT(1);                                                                 \
        __syncthreads();                                                            \
        if (t + 2 < T)                                                              \
            gemm_load_tile_h(A, B, K, t + 2, sbase + ((t + 2) % GSTG) * STAGE_B, tid); \
        uint32_t sa = sbase + (t % GSTG) * STAGE_B;                                 \
        uint32_t sb = sa + TB_A;                                                    \
        _Pragma("unroll")                                                           \
        for (int ks = 0; ks < 4; ks++) {                                            \
            uint32_t afr[4][4];                                                     \
            _Pragma("unroll")                                                       \
            for (int mt = 0; mt < 4; mt++) {                                        \
                uint32_t row = (uint32_t)(a_row + mt * 16);                         \
                uint32_t c = (uint32_t)ks * 32 + a_kb;                              \
                ldsm_x4(afr[mt], sa + row * 128 + (c ^ ((row & 7) << 4)));          \
            }                                                                       \
            uint32_t bfr[4][4];                                                     \
            _Pragma("unroll")                                                       \
            for (int nh = 0; nh < 4; nh++) {                                        \
                uint32_t row = (uint32_t)(b_row + nh * 16);                         \
                uint32_t c = (uint32_t)ks * 32 + b_kb;                              \
                ldsm_x4(bfr[nh], sb + row * 128 + (c ^ ((row & 7) << 4)));          \
            }                                                                       \
            _Pragma("unroll")                                                       \
            for (int mt = 0; mt < 4; mt++)                                          \
                _Pragma("unroll")                                                   \
                for (int nt = 0; nt < 8; nt++)                                      \
                    mma_fp16(acc[mt][nt], afr[mt], &bfr[nt >> 1][(nt & 1) * 2]);    \
        }                                                                           \
    }

// fp32-output GEMM (out_proj)
__global__ __launch_bounds__(128, 2) void gemm_hc(const __half* __restrict__ A,
                                                  const __half* __restrict__ B,
                                                  float* __restrict__ C,
                                                  int K, int ldc) {
    extern __shared__ char sm[];
    uint32_t sbase = smem_u32(sm);
    int tid = threadIdx.x, lane = tid & 31, wid = tid >> 5;
    int wm = (wid & 1) * 64, wn = (wid >> 1) * 64;
    int m0 = blockIdx.y * GBM, n0 = blockIdx.x * GBN;
    const __half* Ab = A + (size_t)m0 * K;
    const __half* Bb = B + (size_t)n0 * K;
    int a_row = wm + (lane & 15);
    uint32_t a_kb = (uint32_t)(lane >> 4) * 16;
    int b_row = wn + (lane & 7) + ((lane & 16) ? 8 : 0);
    uint32_t b_kb = (lane & 8) ? 16u : 0u;

    float acc[4][8][4];
    #pragma unroll
    for (int mt = 0; mt < 4; mt++)
        #pragma unroll
        for (int nt = 0; nt < 8; nt++)
            #pragma unroll
            for (int q = 0; q < 4; q++) acc[mt][nt][q] = 0.f;

    GEMM_MAIN(acc, Ab, Bb, K)

    int g = lane >> 2, tg = lane & 3;
    #pragma unroll
    for (int mt = 0; mt < 4; mt++) {
        int rowa = m0 + wm + mt * 16 + g;
        #pragma unroll
        for (int nt = 0; nt < 8; nt++) {
            int col = n0 + wn + nt * 8 + tg * 2;
            *(float2*)(C + (size_t)rowa * ldc + col) =
                make_float2(acc[mt][nt][0], acc[mt][nt][1]);
            *(float2*)(C + (size_t)(rowa + 8) * ldc + col) =
                make_float2(acc[mt][nt][2], acc[mt][nt][3]);
        }
    }
}

// fp16-output GEMM (in_proj) with fp32 dt side-channel
__global__ __launch_bounds__(128, 2) void gemm_hc_h(const __half* __restrict__ A,
                                                    const __half* __restrict__ B,
                                                    __half* __restrict__ C,
                                                    int K, int ldc) {
    extern __shared__ char sm[];
    uint32_t sbase = smem_u32(sm);
    int tid = threadIdx.x, lane = tid & 31, wid = tid >> 5;
    int wm = (wid & 1) * 64, wn = (wid >> 1) * 64;
    int m0 = blockIdx.y * GBM, n0 = blockIdx.x * GBN;
    const __half* Ab = A + (size_t)m0 * K;
    const __half* Bb = B + (size_t)n0 * K;
    int a_row = wm + (lane & 15);
    uint32_t a_kb = (uint32_t)(lane >> 4) * 16;
    int b_row = wn + (lane & 7) + ((lane & 16) ? 8 : 0);
    uint32_t b_kb = (lane & 8) ? 16u : 0u;

    float acc[4][8][4];
    #pragma unroll
    for (int mt = 0; mt < 4; mt++)
        #pragma unroll
        for (int nt = 0; nt < 8; nt++)
            #pragma unroll
            for (int q = 0; q < 4; q++) acc[mt][nt][q] = 0.f;

    GEMM_MAIN(acc, Ab, Bb, K)

    int g = lane >> 2, tg = lane & 3;
    #pragma unroll
    for (int mt = 0; mt < 4; mt++) {
        int rowa = m0 + wm + mt * 16 + g;
        #pragma unroll
        for (int nt = 0; nt < 8; nt++) {
            int col = n0 + wn + nt * 8 + tg * 2;
            *(uint32_t*)(C + (size_t)rowa * ldc + col) =
                pack2(acc[mt][nt][0], acc[mt][nt][1]);
            *(uint32_t*)(C + (size_t)(rowa + 8) * ldc + col) =
                pack2(acc[mt][nt][2], acc[mt][nt][3]);
            if (col >= DT_BASE && col < DPROJ) {
                int d = col - DT_BASE;
                g_dtraw[(size_t)rowa * NHEADS + d]     = acc[mt][nt][0];
                g_dtraw[(size_t)rowa * NHEADS + d + 1] = acc[mt][nt][1];
                g_dtraw[(size_t)(rowa + 8) * NHEADS + d]     = acc[mt][nt][2];
                g_dtraw[(size_t)(rowa + 8) * NHEADS + d + 1] = acc[mt][nt][3];
            }
        }
    }
}

// ============ K6a (fp16 MMA): S tile = C @ B^T, K=64 (fp16 S out) ============
__global__ __launch_bounds__(256, 2) void k_scores_h() {
    __shared__ __align__(16) __half As[128 * 64];
    __shared__ __align__(16) __half Bs[128 * 64];
    int bc = blockIdx.x;
    int tile = blockIdx.y;
    int i0 = (tile != 0) ? 128 : 0;
    int j0 = (tile == 2) ? 128 : 0;
    int row0 = bc * CHUNK;
    int tid = threadIdx.x, lane = tid & 31, wid = tid >> 5;

    uint32_t as_base = smem_u32(As);
    uint32_t bs_base = smem_u32(Bs);
    const __half* Cb = g_xBCh + (size_t)(row0 + i0) * CONVDIM + D_INNER + D_STATE;
    const __half* Bb = g_xBCh + (size_t)(row0 + j0) * CONVDIM + D_INNER;
    #pragma unroll
    for (int j = 0; j < 4; j++) {
        int c = tid + 256 * j;
        int row = c >> 3;
        uint32_t cc = (uint32_t)(c & 7) * 16;
        uint32_t off = (uint32_t)row * 128 + (cc ^ (((uint32_t)row & 7) << 4));
        CP_ASYNC16(as_base + off, Cb + (size_t)row * CONVDIM + (cc >> 1));
        CP_ASYNC16(bs_base + off, Bb + (size_t)row * CONVDIM + (cc >> 1));
    }
    CP_COMMIT();
    CP_WAIT(0);
    __syncthreads();

    int wm = (wid & 3) * 32;
    int wn = (wid >> 2) * 64;
    int a_row = wm + (lane & 15);
    uint32_t a_kb = (uint32_t)(lane >> 4) * 16;
    int b_row = wn + (lane & 7) + ((lane & 16) ? 8 : 0);
    uint32_t b_kb = (lane & 8) ? 16u : 0u;

    float acc[2][8][4];
    #pragma unroll
    for (int mt = 0; mt < 2; mt++)
        #pragma unroll
        for (int nt = 0; nt < 8; nt++)
            #pragma unroll
            for (int q = 0; q < 4; q++) acc[mt][nt][q] = 0.f;

    #pragma unroll
    for (int ks = 0; ks < 4; ks++) {
        uint32_t afr[2][4];
        #pragma unroll
        for (int mt = 0; mt < 2; mt++) {
            uint32_t row = (uint32_t)(a_row + mt * 16);
            uint32_t c = (uint32_t)ks * 32 + a_kb;
            ldsm_x4(afr[mt], as_base + row * 128 + (c ^ ((row & 7) << 4)));
        }
        uint32_t bfr[4][4];
        #pragma unroll
        for (int nh = 0; nh < 4; nh++) {
            uint32_t row = (uint32_t)(b_row + nh * 16);
            uint32_t c = (uint32_t)ks * 32 + b_kb;
            ldsm_x4(bfr[nh], bs_base + row * 128 + (c ^ ((row & 7) << 4)));
        }
        #pragma unroll
        for (int mt = 0; mt < 2; mt++)
            #pragma unroll
            for (int nt = 0; nt < 8; nt++)
                mma_fp16(acc[mt][nt], afr[mt], &bfr[nt >> 1][(nt & 1) * 2]);
    }

    int g = lane >> 2, tg = lane & 3;
    #pragma unroll
    for (int mt = 0; mt < 2; mt++) {
        int irow = i0 + wm + mt * 16 + g;
        #pragma unroll
        for (int nt = 0; nt < 8; nt++) {
            int col = j0 + wn + nt * 8 + tg * 2;
            *(uint32_t*)(g_Sh + ((size_t)bc * CHUNK + irow) * CHUNK + col) =
                pack2(acc[mt][nt][0], acc[mt][nt][1]);
            *(uint32_t*)(g_Sh + ((size_t)bc * CHUNK + irow + 8) * CHUNK + col) =
                pack2(acc[mt][nt][2], acc[mt][nt][3]);
        }
    }
}

// ============ K7 (fp16 MMA): states[p][n] = sum_t (x[t][p]*w_t) * B[t][n] ============
__global__ __launch_bounds__(256, 2) void k_states_h() {
    __shared__ __align__(16) __half As[128 * 64];
    __shared__ __align__(16) __half Bs[64 * 64];
    __shared__ float wsh[256];
    int bc = blockIdx.x, h = blockIdx.y;
    int row0 = bc * CHUNK;
    int cb = (bc * NHEADS + h) * CHUNK;
    int tid = threadIdx.x, lane = tid & 31, wid = tid >> 5;

    float cum_last = g_cum[cb + 255];
    wsh[tid] = g_dt[(size_t)(row0 + tid) * NHEADS + h] *
               __expf(cum_last - g_cum[cb + tid]);

    uint32_t as_base = smem_u32(As);
    uint32_t bs_base = smem_u32(Bs);

    int wm = (wid & 3) * 32;
    int wn = (wid >> 2) * 32;
    int a_row = wm + (lane & 15);
    uint32_t a_kb = (uint32_t)(lane >> 4) * 16;
    int b_row = wn + (lane & 7) + ((lane & 16) ? 8 : 0);
    uint32_t b_kb = (lane & 8) ? 16u : 0u;

    float acc[2][4][4];
    #pragma unroll
    for (int mt = 0; mt < 2; mt++)
        #pragma unroll
        for (int nt = 0; nt < 4; nt++)
            #pragma unroll
            for (int q = 0; q < 4; q++) acc[mt][nt][q] = 0.f;

    for (int kt = 0; kt < 4; kt++) {
        int t0 = kt * 64;
        __syncthreads();
        #pragma unroll
        for (int jp = 0; jp < 4; jp++) {
            int pair = wid + 8 * jp;
            int t = t0 + 2 * pair;
            const __half* x0 = g_xBCh + (size_t)(row0 + t) * CONVDIM + h * HEADDIM;
            const __half* x1 = x0 + CONVDIM;
            float w0 = wsh[t], w1 = wsh[t + 1];
            #pragma unroll
            for (int r = 0; r < 4; r++) {
                int p = lane + 32 * r;
                uint32_t cbyte = (uint32_t)pair * 4;
                uint32_t off = (uint32_t)p * 128 + (cbyte ^ (((uint32_t)p & 7) << 4));
                *(uint32_t*)((char*)As + off) =
                    pack2(__half2float(x0[p]) * w0, __half2float(x1[p]) * w1);
            }
        }
        #pragma unroll
        for (int q = 0; q < 8; q++) {
            int idx = tid + 256 * q;
            int n = idx >> 5, pair = idx & 31;
            int t = t0 + 2 * pair;
            const __half* b0 = g_xBCh + (size_t)(row0 + t) * CONVDIM + D_INNER;
            uint32_t cbyte = (uint32_t)pair * 4;
            uint32_t off = (uint32_t)n * 128 + (cbyte ^ (((uint32_t)n & 7) << 4));
            *(uint32_t*)((char*)Bs + off) = pack2h(b0[n], b0[CONVDIM + n]);
        }
        __syncthreads();
        #pragma unroll
        for (int ks = 0; ks < 4; ks++) {
            uint32_t afr[2][4];
            #pragma unroll
            for (int mt = 0; mt < 2; mt++) {
                uint32_t row = (uint32_t)(a_row + mt * 16);
                uint32_t c = (uint32_t)ks * 32 + a_kb;
                ldsm_x4(afr[mt], as_base + row * 128 + (c ^ ((row & 7) << 4)));
            }
            uint32_t bfr[2][4];
            #pragma unroll
            for (int nh = 0; nh < 2; nh++) {
                uint32_t row = (uint32_t)(b_row + nh * 16);
                uint32_t c = (uint32_t)ks * 32 + b_kb;
                ldsm_x4(bfr[nh], bs_base + row * 128 + (c ^ ((row & 7) << 4)));
            }
            #pragma unroll
            for (int mt = 0; mt < 2; mt++)
                #pragma unroll
                for (int nt = 0; nt < 4; nt++)
                    mma_fp16(acc[mt][nt], afr[mt], &bfr[nt >> 1][(nt & 1) * 2]);
        }
    }

    size_t base = (size_t)(bc * NHEADS + h) * HEADDIM * D_STATE;
    int g = lane >> 2, tg = lane & 3;
    #pragma unroll
    for (int mt = 0; mt < 2; mt++) {
        int prow = wm + mt * 16 + g;
        #pragma unroll
        for (int nt = 0; nt < 4; nt++) {
            int col = wn + nt * 8 + tg * 2;
            *(float2*)(g_st + base + (size_t)prow * D_STATE + col) =
                make_float2(acc[mt][nt][0], acc[mt][nt][1]);
            *(float2*)(g_st + base + (size_t)(prow + 8) * D_STATE + col) =
                make_float2(acc[mt][nt][2], acc[mt][nt][3]);
        }
    }
}

// ============ fused SSD y-kernel (fp16 fragments, fp32 accumulate, fp16 y out) ============
__global__ __launch_bounds__(256, 2) void k_yfused() {
    __shared__ __align__(16) __half As[128 * 64];
    __shared__ __align__(16) __half Bs[128 * 64];
    __shared__ float gj_all[256];
    __shared__ float cas[8];
    int bc = blockIdx.x, h = blockIdx.y, ih = blockIdx.z;
    int i_base = ih * 128;
    int row0 = bc * CHUNK;
    int cb = (bc * NHEADS + h) * CHUNK;
    size_t psb = (size_t)(bc * NHEADS + h) * HEADDIM * D_STATE;

    int tid = threadIdx.x, lane = tid & 31, wid = tid >> 5;
    int wm = (wid & 3) * 32;
    int wn = (wid >> 2) * 64;

    int si = tid >> 1;
    int sj = (tid & 1) * 32;
    int gi = i_base + si;
    float ci = g_cum[cb + gi];
    float ei = __expf(ci);

    uint32_t as_base = smem_u32(As);
    uint32_t bs_base = smem_u32(Bs);

    int a_row = wm + (lane & 15);
    uint32_t a_kb = (uint32_t)(lane >> 4) * 16;
    int b_row = wn + (lane & 7) + ((lane & 16) ? 8 : 0);
    uint32_t b_kb = (lane & 8) ? 16u : 0u;

    int natt64 = (ih + 1) * 2;
    int nattj = natt64 * 64;

    if (tid < nattj) {
        int j = tid;
        float ca = g_cum[cb + (j & ~31) + 31];
        gj_all[j] = __expf(ca - g_cum[cb + j]) *
                    g_dt[(size_t)(row0 + j) * NHEADS + h];
    }
    if (tid < natt64 * 2) cas[tid] = g_cum[cb + tid * 32 + 31];

    float acc[2][8][4];
    #pragma unroll
    for (int mt = 0; mt < 2; mt++)
        #pragma unroll
        for (int nt = 0; nt < 8; nt++)
            #pragma unroll
            for (int q = 0; q < 4; q++) acc[mt][nt][q] = 0.f;

    int ntiles = natt64 + 1;
    for (int kt = 0; kt < ntiles; kt++) {
        __syncthreads();
        if (kt < natt64) {
            int j0 = kt * 64;
            int jb = j0 + sj;
            if (gi >= jb + 31) {
                float fi = __expf(ci - cas[jb >> 5]);
                const __half* Srow = g_Sh + ((size_t)bc * CHUNK + gi) * CHUNK + jb;
                const float* gjp = gj_all + jb;
                #pragma unroll
                for (int q = 0; q < 4; q++) {
                    uint4 sv = *(const uint4*)(Srow + q * 8);
                    float2 f0 = __half22float2(*(__half2*)&sv.x);
                    float2 f1 = __half22float2(*(__half2*)&sv.y);
                    float2 f2 = __half22float2(*(__half2*)&sv.z);
                    float2 f3 = __half22float2(*(__half2*)&sv.w);
                    uint4 u;
                    u.x = pack2(f0.x * fi * gjp[q*8+0], f0.y * fi * gjp[q*8+1]);
                    u.y = pack2(f1.x * fi * gjp[q*8+2], f1.y * fi * gjp[q*8+3]);
                    u.z = pack2(f2.x * fi * gjp[q*8+4], f2.y * fi * gjp[q*8+5]);
                    u.w = pack2(f3.x * fi * gjp[q*8+6], f3.y * fi * gjp[q*8+7]);
                    uint32_t cbyte = (uint32_t)(sj * 2 + q * 16);
                    uint32_t off = (uint32_t)si * 128 + (cbyte ^ (((uint32_t)si & 7) << 4));
                    *(uint4*)((char*)As + off) = u;
                }
            } else if (gi >= jb) {
                #pragma unroll
                for (int q = 0; q < 4; q++) {
                    float v[8];
                    #pragma unroll
                    for (int r = 0; r < 8; r++) {
                        int j = jb + q * 8 + r;
                        float a = 0.f;
                        if (j <= gi)
                            a = __half2float(g_Sh[((size_t)bc * CHUNK + gi) * CHUNK + j]) *
                                __expf(ci - g_cum[cb + j]) *
                                g_dt[(size_t)(row0 + j) * NHEADS + h];
                        v[r] = a;
                    }
                    uint4 u;
                    u.x = pack2(v[0], v[1]); u.y = pack2(v[2], v[3]);
                    u.z = pack2(v[4], v[5]); u.w = pack2(v[6], v[7]);
                    uint32_t cbyte = (uint32_t)(sj * 2 + q * 16);
                    uint32_t off = (uint32_t)si * 128 + (cbyte ^ (((uint32_t)si & 7) << 4));
                    *(uint4*)((char*)As + off) = u;
                }
            } else {
                #pragma unroll
                for (int q = 0; q < 4; q++) {
                    uint32_t cbyte = (uint32_t)(sj * 2 + q * 16);
                    uint32_t off = (uint32_t)si * 128 + (cbyte ^ (((uint32_t)si & 7) << 4));
                    *(uint4*)((char*)As + off) = make_uint4(0, 0, 0, 0);
                }
            }
            #pragma unroll
            for (int jp = 0; jp < 4; jp++) {
                int pair = wid + 8 * jp;
                int j = j0 + 2 * pair;
                const __half* x0 = g_xBCh + (size_t)(row0 + j) * CONVDIM + h * HEADDIM;
                const __half* x1 = x0 + CONVDIM;
                #pragma unroll
                for (int r = 0; r < 4; r++) {
                    int p = lane + 32 * r;
                    uint32_t cbyte = (uint32_t)pair * 4;
                    uint32_t off = (uint32_t)p * 128 + (cbyte ^ (((uint32_t)p & 7) << 4));
                    *(uint32_t*)((char*)Bs + off) = pack2h(x0[p], x1[p]);
                }
            }
        } else {
            const __half2* crow = (const __half2*)(g_xBCh + (size_t)(row0 + gi) * CONVDIM
                                                   + D_INNER + D_STATE + sj);
            #pragma unroll
            for (int q = 0; q < 4; q++) {
                uint4 hv = *(const uint4*)(crow + q * 4);
                float2 f0 = __half22float2(*(__half2*)&hv.x);
                float2 f1 = __half22float2(*(__half2*)&hv.y);
                float2 f2 = __half22float2(*(__half2*)&hv.z);
                float2 f3 = __half22float2(*(__half2*)&hv.w);
                uint4 u;
                u.x = pack2(f0.x * ei, f0.y * ei);
                u.y = pack2(f1.x * ei, f1.y * ei);
                u.z = pack2(f2.x * ei, f2.y * ei);
                u.w = pack2(f3.x * ei, f3.y * ei);
                uint32_t cbyte = (uint32_t)(sj * 2 + q * 16);
                uint32_t off = (uint32_t)si * 128 + (cbyte ^ (((uint32_t)si & 7) << 4));
                *(uint4*)((char*)As + off) = u;
            }
            int pr = tid >> 1;
            int nc = (tid & 1) * 32;
            const __half* prow = g_psh + psb + (size_t)pr * D_STATE + nc;
            #pragma unroll
            for (int q = 0; q < 2; q++) {
                uint4 u = *(const uint4*)(prow + q * 16);
                uint32_t off = (uint32_t)pr * 128 +
                    (((uint32_t)(nc * 2 + q * 32)) ^ (((uint32_t)pr & 7) << 4));
                *(uint4*)((char*)Bs + off) = u;
                uint4 u2 = *(const uint4*)(prow + q * 16 + 8);
                uint32_t off2 = (uint32_t)pr * 128 +
                    (((uint32_t)(nc * 2 + q * 32 + 16)) ^ (((uint32_t)pr & 7) << 4));
                *(uint4*)((char*)Bs + off2) = u2;
            }
        }
        __syncthreads();
        #pragma unroll
        for (int ks = 0; ks < 4; ks++) {
            uint32_t afr[2][4];
            #pragma unroll
            for (int mt = 0; mt < 2; mt++) {
                uint32_t row = (uint32_t)(a_row + mt * 16);
                uint32_t c = (uint32_t)ks * 32 + a_kb;
                ldsm_x4(afr[mt], as_base + row * 128 + (c ^ ((row & 7) << 4)));
            }
            uint32_t bfr[4][4];
            #pragma unroll
            for (int nh = 0; nh < 4; nh++) {
                uint32_t row = (uint32_t)(b_row + nh * 16);
                uint32_t c = (uint32_t)ks * 32 + b_kb;
                ldsm_x4(bfr[nh], bs_base + row * 128 + (c ^ ((row & 7) << 4)));
            }
            #pragma unroll
            for (int mt = 0; mt < 2; mt++)
                #pragma unroll
                for (int nt = 0; nt < 8; nt++)
                    mma_fp16(acc[mt][nt], afr[mt], &bfr[nt >> 1][(nt & 1) * 2]);
        }
    }

    int g = lane >> 2, tg = lane & 3;
    #pragma unroll
    for (int mt = 0; mt < 2; mt++) {
        int orow = row0 + i_base + wm + mt * 16 + g;
        #pragma unroll
        for (int nt = 0; nt < 8; nt++) {
            int col = h * HEADDIM + wn + nt * 8 + tg * 2;
            *(uint32_t*)(g_yh + (size_t)orow * D_INNER + col) =
                pack2(acc[mt][nt][0], acc[mt][nt][1]);
            *(uint32_t*)(g_yh + (size_t)(orow + 8) * D_INNER + col) =
                pack2(acc[mt][nt][2], acc[mt][nt][3]);
        }
    }
}

// ---------------- reductions ----------------
__device__ __forceinline__ float blockReduceSum256(float v) {
    __shared__ float red[8];
    __shared__ float tot;
    int lane = threadIdx.x & 31, wid = threadIdx.x >> 5;
    #pragma unroll
    for (int o = 16; o; o >>= 1) v += __shfl_down_sync(0xffffffffu, v, o);
    if (lane == 0) red[wid] = v;
    __syncthreads();
    if (wid == 0) {
        float w = (lane < 8) ? red[lane] : 0.f;
        #pragma unroll
        for (int o = 4; o; o >>= 1) w += __shfl_down_sync(0xffffffffu, w, o);
        if (lane == 0) tot = w;
    }
    __syncthreads();
    return tot;
}

// ---------------- K1: l2-normalize weight rows ----------------
__global__ __launch_bounds__(256) void k_normw(const float* __restrict__ W,
                                               __half* __restrict__ Wo, int K, float extra) {
    int r = blockIdx.x;
    const float* wr = W + (size_t)r * K;
    float s2 = 0.f;
    for (int i = threadIdx.x; i < K; i += 256) { float v = wr[i]; s2 += v * v; }
    float totv = blockReduceSum256(s2);
    float sc = extra / fmaxf(sqrtf(totv), 1e-6f);
    for (int i = threadIdx.x; i < K; i += 256)
        Wo[(size_t)r * K + i] = __float2half_rn(wr[i] * sc);
}

// ---------------- K2: layernorm ----------------
__global__ __launch_bounds__(256) void k_layernorm(const float* __restrict__ u,
                                                   const float* __restrict__ w,
                                                   const float* __restrict__ b) {
    int row = blockIdx.x;
    const float* ur = u + (size_t)row * XDIM;
    float v[4]; float s = 0.f, s2 = 0.f;
    #pragma unroll
    for (int k = 0; k < 4; k++) {
        v[k] = ur[threadIdx.x + 256 * k];
        s += v[k]; s2 += v[k] * v[k];
    }
    float sum = blockReduceSum256(s);
    float sumsq = blockReduceSum256(s2);
    float mu = sum * (1.f / XDIM);
    float var = sumsq * (1.f / XDIM) - mu * mu;
    float inv = rsqrtf(var + 1e-5f);
    #pragma unroll
    for (int k = 0; k < 4; k++) {
        int d = threadIdx.x + 256 * k;
        g_lnh[(size_t)row * XDIM + d] = __float2half_rn((v[k] - mu) * inv * w[d] + b[d]);
    }
}

// ---------------- K4: depthwise causal conv + bias + silu ----------------
__global__ __launch_bounds__(128) void k_conv(const float* __restrict__ cw,
                                              const float* __restrict__ cb) {
    int ch = blockIdx.x * 128 + threadIdx.x;
    if (ch >= CONVDIM) return;
    int row0 = blockIdx.y * 8;
    int l0 = row0 & (SEQLEN - 1);
    float w0 = cw[ch * 4 + 0], w1 = cw[ch * 4 + 1];
    float w2 = cw[ch * 4 + 2], w3 = cw[ch * 4 + 3];
    float bias = cb[ch];
    float v[11];
    #pragma unroll
    for (int k = 0; k < 11; k++) {
        int l = l0 - 3 + k;
        v[k] = (l >= 0)
            ? __half2float(g_zxh[(size_t)(row0 - 3 + k) * DPROJP + D_INNER + ch]) : 0.f;
    }
    #pragma unroll
    for (int r = 0; r < 8; r++) {
        float acc = bias + w0 * v[r] + w1 * v[r + 1] + w2 * v[r + 2] + w3 * v[r + 3];
        float s = acc / (1.f + __expf(-acc));
        g_xBCh[(size_t)(row0 + r) * CONVDIM + ch] = __float2half_rn(s);
    }
}

// ---------------- K5: dt softplus + per-chunk cumulative dA (warp-shuffle scan) ----------------
__global__ __launch_bounds__(256) void k_dtcum(const float* __restrict__ dt_bias,
                                               const float* __restrict__ A_log) {
    __shared__ float wsum[8];
    int bch = blockIdx.x;
    int h = bch & 15, bc = bch >> 4;
    int t = threadIdx.x;
    int lane = t & 31, wrp = t >> 5;
    int row = bc * CHUNK + t;
    float x = g_dtraw[(size_t)row * NHEADS + h] + dt_bias[h];
    float dtv = (x > 20.f) ? x : log1pf(expf(x));
    g_dt[(size_t)row * NHEADS + h] = dtv;
    float dA = dtv * (-expf(A_log[h]));
    // inclusive warp scan
    float v = dA;
    #pragma unroll
    for (int o = 1; o < 32; o <<= 1) {
        float p = __shfl_up_sync(0xffffffffu, v, o);
        if (lane >= o) v += p;
    }
    if (lane == 31) wsum[wrp] = v;
    __syncthreads();
    float base = 0.f;
    #pragma unroll
    for (int w = 0; w < 8; w++)
        if (w < wrp) base += wsum[w];
    float s = base + v;
    g_cum[(size_t)bch * CHUNK + t] = s;
    if (t == 255) g_cdec[bch] = __expf(s);
}

// ---------------- K8: inter-chunk scan (fp32 carry, fp16 ps out) ----------------
__global__ __launch_bounds__(256) void k_scan() {
    int b = blockIdx.x, h = blockIdx.y, z = blockIdx.z;
    int tid = threadIdx.x;
    int e0 = z * 1024 + tid * 4;
    float4 carry = make_float4(0.f, 0.f, 0.f, 0.f);
    for (int c = 0; c < NCPB; c++) {
        int bch = (b * NCPB + c) * NHEADS + h;
        float dec = g_cdec[bch];
        size_t base = (size_t)bch * HEADDIM * D_STATE + e0;
        uint2 pk;
        pk.x = pack2(carry.x, carry.y);
        pk.y = pack2(carry.z, carry.w);
        *(uint2*)(g_psh + base) = pk;
        float4 st = *(const float4*)(g_st + base);
        carry.x = carry.x * dec + st.x;
        carry.y = carry.y * dec + st.y;
        carry.z = carry.z * dec + st.z;
        carry.w = carry.w * dec + st.w;
    }
}

// ---------------- K10: y += D*x, gate, RMS norm ----------------
__global__ __launch_bounds__(256) void k_gate(const float* __restrict__ Dp,
                                              const float* __restrict__ rms_w) {
    int row = blockIdx.x;
    int tid = threadIdx.x;
    float gg[8];
    float s2 = 0.f;
    #pragma unroll
    for (int k = 0; k < 8; k++) {
        int d = tid + 256 * k;
        float xv = __half2float(g_xBCh[(size_t)row * CONVDIM + d]);
        float yv = __half2float(g_yh[(size_t)row * D_INNER + d]);
        float v = yv + Dp[d >> 7] * xv;
        float z = __half2float(g_zxh[(size_t)row * DPROJP + d]);
        float sil = z / (1.f + __expf(-z));
        float g = v * sil;
        gg[k] = g;
        s2 += g * g;
    }
    float tot = blockReduceSum256(s2);
    float sc = rsqrtf(tot * (1.f / D_INNER) + 1e-5f);
    #pragma unroll
    for (int k = 0; k < 8; k++) {
        int d = tid + 256 * k;
        g_gh[(size_t)row * D_INNER + d] = __float2half_rn(gg[k] * sc * rms_w[d]);
    }
}

// ---------------- host launcher ----------------
extern "C" void kernel_launch(void* const* d_in, const int* in_sizes, int n_in,
                              void* d_out, int out_size) {
    const float* u          = (const float*)d_in[0];
    const float* in_proj_w  = (const float*)d_in[1];
    const float* conv_w     = (const float*)d_in[2];
    const float* conv_b     = (const float*)d_in[3];
    const float* dt_bias    = (const float*)d_in[4];
    const float* A_log      = (const float*)d_in[5];
    const float* Dp         = (const float*)d_in[6];
    const float* xnw        = (const float*)d_in[7];
    const float* xnb        = (const float*)d_in[8];
    const float* rms_w      = (const float*)d_in[9];
    const float* out_proj_w = (const float*)d_in[10];
    float* out = (float*)d_out;

    __half *pWinH, *pWoutH, *pLnH, *pGH, *pZxH;
    cudaGetSymbolAddress((void**)&pWinH,  g_Winh);
    cudaGetSymbolAddress((void**)&pWoutH, g_Wouth);
    cudaGetSymbolAddress((void**)&pLnH,   g_lnh);
    cudaGetSymbolAddress((void**)&pGH,    g_gh);
    cudaGetSymbolAddress((void**)&pZxH,   g_zxh);

    static int smem_set = 0;
    if (!smem_set) {
        cudaFuncSetAttribute(gemm_hc, cudaFuncAttributeMaxDynamicSharedMemorySize, GEMM_SMEM);
        cudaFuncSetAttribute(gemm_hc_h, cudaFuncAttributeMaxDynamicSharedMemorySize, GEMM_SMEM);
        smem_set = 1;
    }

    k_normw<<<DPROJ, 256>>>(in_proj_w, pWinH, XDIM, 0.03125f);
    k_normw<<<XDIM, 256>>>(out_proj_w, pWoutH, D_INNER, 1.0f);

    k_layernorm<<<R_TOT, 256>>>(u, xnw, xnb);

    gemm_hc_h<<<dim3(DPROJP / GBN, R_TOT / GBM), 128, GEMM_SMEM>>>(pLnH, pWinH, pZxH, XDIM, DPROJP);

    k_conv<<<dim3((CONVDIM + 127) / 128, R_TOT / 8), 128>>>(conv_w, conv_b);
    k_dtcum<<<NBC * NHEADS, 256>>>(dt_bias, A_log);

    k_scores_h<<<dim3(NBC, 3), 256>>>();
    k_states_h<<<dim3(NBC, NHEADS), 256>>>();
    k_scan<<<dim3(NBATCH, NHEADS, 8), 256>>>();
    k_yfused<<<dim3(NBC, NHEADS, 2), 256>>>();

    k_gate<<<R_TOT, 256>>>(Dp, rms_w);

    gemm_hc<<<dim3(XDIM / GBN, R_TOT / GBM), 128, GEMM_SMEM>>>(pGH, pWoutH, out, D_INNER, XDIM);
}

// round 16
// speedup vs baseline: 1.0423x; 1.0367x over previous
#include <cuda_runtime.h>
#include <cuda_fp16.h>
#include <math.h>
#include <stdint.h>

// ---------------- problem constants ----------------
#define XDIM    1024
#define D_STATE 64
#define HEADDIM 128
#define D_INNER 2048
#define NHEADS  16
#define CONVDIM 2176              // D_INNER + 2*64
#define DPROJ   4240              // 2*2048 + 2*64 + 16
#define DPROJP  4352              // padded to 128-multiple for GEMM tiles
#define DT_BASE 4224              // D_INNER + CONVDIM
#define CHUNK   256
#define NBATCH  2
#define SEQLEN  4096
#define NCPB    16
#define NBC     32
#define R_TOT   8192

// ---------------- device scratch ----------------
__device__ __half g_lnh [(size_t)R_TOT * XDIM];
__device__ __half g_Winh[(size_t)DPROJP * XDIM];     // rows >= DPROJ stay zero (.bss)
__device__ __half g_Wouth[(size_t)XDIM * D_INNER];
__device__ __half g_gh  [(size_t)R_TOT * D_INNER];
__device__ __half g_zxh [(size_t)R_TOT * DPROJP];    // fp16 in_proj output
__device__ __half g_xBCh[(size_t)R_TOT * CONVDIM];   // fp16 conv output
__device__ __half g_yh  [(size_t)R_TOT * D_INNER];   // fp16 y
__device__ __half g_Sh  [(size_t)NBC * CHUNK * CHUNK];  // fp16 scores
__device__ __half g_psh [(size_t)NBC * NHEADS * HEADDIM * D_STATE];  // fp16 prev states
__device__ float g_dtraw[(size_t)R_TOT * NHEADS];    // fp32 dt_raw side-channel
__device__ float g_dt  [(size_t)R_TOT * NHEADS];
__device__ float g_cum [(size_t)NBC * NHEADS * CHUNK];
__device__ float g_cdec[(size_t)NBC * NHEADS];
__device__ float g_st  [(size_t)NBC * NHEADS * HEADDIM * D_STATE];

// ---------------- PTX helpers (baseline PTX only) ----------------
__device__ __forceinline__ uint32_t smem_u32(const void* p) {
    uint32_t a;
    asm("{ .reg .u64 t; cvta.to.shared.u64 t, %1; cvt.u32.u64 %0, t; }" : "=r"(a) : "l"(p));
    return a;
}
__device__ __forceinline__ uint32_t pack2(float a, float b) {
    __half2 h = __floats2half2_rn(a, b);
    return *(uint32_t*)&h;
}
__device__ __forceinline__ uint32_t pack2h(__half a, __half b) {
    __half2 h = __halves2half2(a, b);
    return *(uint32_t*)&h;
}
#define CP_ASYNC16(s, g) \
    asm volatile("cp.async.cg.shared.global [%0], [%1], 16;" :: "r"(s), "l"(g))
#define CP_COMMIT() asm volatile("cp.async.commit_group;" ::: "memory")
#define CP_WAIT(n)  asm volatile("cp.async.wait_group %0;" :: "n"(n) : "memory")

__device__ __forceinline__ void ldsm_x4(uint32_t* r, uint32_t addr) {
    asm volatile("ldmatrix.sync.aligned.m8n8.x4.shared.b16 {%0,%1,%2,%3}, [%4];"
        : "=r"(r[0]), "=r"(r[1]), "=r"(r[2]), "=r"(r[3]) : "r"(addr));
}
__device__ __forceinline__ void mma_fp16(float* d, const uint32_t* a, const uint32_t* b) {
    asm volatile("mma.sync.aligned.m16n8k16.row.col.f32.f16.f16.f32 "
        "{%0,%1,%2,%3},{%4,%5,%6,%7},{%8,%9},{%0,%1,%2,%3};"
        : "+f"(d[0]), "+f"(d[1]), "+f"(d[2]), "+f"(d[3])
        : "r"(a[0]), "r"(a[1]), "r"(a[2]), "r"(a[3]), "r"(b[0]), "r"(b[1]));
}

// ================= fp16 tensor-core GEMM =================
#define GBM 128
#define GBN 128
#define GBK 64
#define GSTG 3
#define TB_A (GBM * GBK * 2)
#define TB_B (GBN * GBK * 2)
#define STAGE_B (TB_A + TB_B)
#define GEMM_SMEM (GSTG * STAGE_B)

__device__ __forceinline__ void gemm_load_tile_h(const __half* Ab, const __half* Bb,
                                                 int K, int t, uint32_t sb, int tid) {
    const __half* Ap = Ab + (size_t)t * GBK;
    const __half* Bp = Bb + (size_t)t * GBK;
    #pragma unroll
    for (int j = 0; j < 8; j++) {
        int c = tid + 128 * j;
        int row = c >> 3;
        uint32_t cc = (uint32_t)(c & 7) * 16;
        uint32_t off = (uint32_t)row * 128 + (cc ^ (((uint32_t)row & 7) << 4));
        CP_ASYNC16(sb + off, Ap + (size_t)row * K + (cc >> 1));
    }
    uint32_t sb2 = sb + TB_A;
    #pragma unroll
    for (int j = 0; j < 8; j++) {
        int c = tid + 128 * j;
        int row = c >> 3;
        uint32_t cc = (uint32_t)(c & 7) * 16;
        uint32_t off = (uint32_t)row * 128 + (cc ^ (((uint32_t)row & 7) << 4));
        CP_ASYNC16(sb2 + off, Bp + (size_t)row * K + (cc >> 1));
    }
    CP_COMMIT();
}

#define GEMM_MAIN(acc, A, B, K)                                                     \
    int T = (K) / GBK;                                                              \
    gemm_load_tile_h(A, B, K, 0, sbase, tid);                                       \
    gemm_load_tile_h(A, B, K, 1, sbase + STAGE_B, tid);                             \
    for (int t = 0; t < T; t++) {                                                   \
        CP_WAIT(1);                                                                 \
        __syncthreads();                                                            \
        if (t + 2 < T)                                                              \
            gemm_load_tile_h(A, B, K, t + 2, sbase + ((t + 2) % GSTG) * STAGE_B, tid); \
        uint32_t sa = sbase + (t % GSTG) * STAGE_B;                                 \
        uint32_t sb = sa + TB_A;                                                    \
        _Pragma("unroll")                                                           \
        for (int ks = 0; ks < 4; ks++) {                                            \
            uint32_t afr[4][4];                                                     \
            _Pragma("unroll")                                                       \
            for (int mt = 0; mt < 4; mt++) {                                        \
                uint32_t row = (uint32_t)(a_row + mt * 16);                         \
                uint32_t c = (uint32_t)ks * 32 + a_kb;                              \
                ldsm_x4(afr[mt], sa + row * 128 + (c ^ ((row & 7) << 4)));          \
            }                                                                       \
            uint32_t bfr[4][4];                                                     \
            _Pragma("unroll")                                                       \
            for (int nh = 0; nh < 4; nh++) {                                        \
                uint32_t row = (uint32_t)(b_row + nh * 16);                         \
                uint32_t c = (uint32_t)ks * 32 + b_kb;                              \
                ldsm_x4(bfr[nh], sb + row * 128 + (c ^ ((row & 7) << 4)));          \
            }                                                                       \
            _Pragma("unroll")                                                       \
            for (int mt = 0; mt < 4; mt++)                                          \
                _Pragma("unroll")                                                   \
                for (int nt = 0; nt < 8; nt++)                                      \
                    mma_fp16(acc[mt][nt], afr[mt], &bfr[nt >> 1][(nt & 1) * 2]);    \
        }                                                                           \
    }

// fp32-output GEMM (out_proj)
__global__ __launch_bounds__(128, 2) void gemm_hc(const __half* __restrict__ A,
                                                  const __half* __restrict__ B,
                                                  float* __restrict__ C,
                                                  int K, int ldc) {
    extern __shared__ char sm[];
    uint32_t sbase = smem_u32(sm);
    int tid = threadIdx.x, lane = tid & 31, wid = tid >> 5;
    int wm = (wid & 1) * 64, wn = (wid >> 1) * 64;
    int m0 = blockIdx.y * GBM, n0 = blockIdx.x * GBN;
    const __half* Ab = A + (size_t)m0 * K;
    const __half* Bb = B + (size_t)n0 * K;
    int a_row = wm + (lane & 15);
    uint32_t a_kb = (uint32_t)(lane >> 4) * 16;
    int b_row = wn + (lane & 7) + ((lane & 16) ? 8 : 0);
    uint32_t b_kb = (lane & 8) ? 16u : 0u;

    float acc[4][8][4];
    #pragma unroll
    for (int mt = 0; mt < 4; mt++)
        #pragma unroll
        for (int nt = 0; nt < 8; nt++)
            #pragma unroll
            for (int q = 0; q < 4; q++) acc[mt][nt][q] = 0.f;

    GEMM_MAIN(acc, Ab, Bb, K)

    int g = lane >> 2, tg = lane & 3;
    #pragma unroll
    for (int mt = 0; mt < 4; mt++) {
        int rowa = m0 + wm + mt * 16 + g;
        #pragma unroll
        for (int nt = 0; nt < 8; nt++) {
            int col = n0 + wn + nt * 8 + tg * 2;
            *(float2*)(C + (size_t)rowa * ldc + col) =
                make_float2(acc[mt][nt][0], acc[mt][nt][1]);
            *(float2*)(C + (size_t)(rowa + 8) * ldc + col) =
                make_float2(acc[mt][nt][2], acc[mt][nt][3]);
        }
    }
}

// fp16-output GEMM (in_proj) with fp32 dt side-channel
__global__ __launch_bounds__(128, 2) void gemm_hc_h(const __half* __restrict__ A,
                                                    const __half* __restrict__ B,
                                                    __half* __restrict__ C,
                                                    int K, int ldc) {
    extern __shared__ char sm[];
    uint32_t sbase = smem_u32(sm);
    int tid = threadIdx.x, lane = tid & 31, wid = tid >> 5;
    int wm = (wid & 1) * 64, wn = (wid >> 1) * 64;
    int m0 = blockIdx.y * GBM, n0 = blockIdx.x * GBN;
    const __half* Ab = A + (size_t)m0 * K;
    const __half* Bb = B + (size_t)n0 * K;
    int a_row = wm + (lane & 15);
    uint32_t a_kb = (uint32_t)(lane >> 4) * 16;
    int b_row = wn + (lane & 7) + ((lane & 16) ? 8 : 0);
    uint32_t b_kb = (lane & 8) ? 16u : 0u;

    float acc[4][8][4];
    #pragma unroll
    for (int mt = 0; mt < 4; mt++)
        #pragma unroll
        for (int nt = 0; nt < 8; nt++)
            #pragma unroll
            for (int q = 0; q < 4; q++) acc[mt][nt][q] = 0.f;

    GEMM_MAIN(acc, Ab, Bb, K)

    int g = lane >> 2, tg = lane & 3;
    bool has_dt = (n0 + GBN) > DT_BASE;   // only the last N-tile carries dt columns
    #pragma unroll
    for (int mt = 0; mt < 4; mt++) {
        int rowa = m0 + wm + mt * 16 + g;
        #pragma unroll
        for (int nt = 0; nt < 8; nt++) {
            int col = n0 + wn + nt * 8 + tg * 2;
            *(uint32_t*)(C + (size_t)rowa * ldc + col) =
                pack2(acc[mt][nt][0], acc[mt][nt][1]);
            *(uint32_t*)(C + (size_t)(rowa + 8) * ldc + col) =
                pack2(acc[mt][nt][2], acc[mt][nt][3]);
            if (has_dt && col >= DT_BASE && col < DPROJ) {
                int d = col - DT_BASE;
                g_dtraw[(size_t)rowa * NHEADS + d]     = acc[mt][nt][0];
                g_dtraw[(size_t)rowa * NHEADS + d + 1] = acc[mt][nt][1];
                g_dtraw[(size_t)(rowa + 8) * NHEADS + d]     = acc[mt][nt][2];
                g_dtraw[(size_t)(rowa + 8) * NHEADS + d + 1] = acc[mt][nt][3];
            }
        }
    }
}

// ============ K6a (fp16 MMA): S tile = C @ B^T, K=64 (fp16 S out) ============
__global__ __launch_bounds__(256, 2) void k_scores_h() {
    __shared__ __align__(16) __half As[128 * 64];
    __shared__ __align__(16) __half Bs[128 * 64];
    int bc = blockIdx.x;
    int tile = blockIdx.y;
    int i0 = (tile != 0) ? 128 : 0;
    int j0 = (tile == 2) ? 128 : 0;
    int row0 = bc * CHUNK;
    int tid = threadIdx.x, lane = tid & 31, wid = tid >> 5;

    uint32_t as_base = smem_u32(As);
    uint32_t bs_base = smem_u32(Bs);
    const __half* Cb = g_xBCh + (size_t)(row0 + i0) * CONVDIM + D_INNER + D_STATE;
    const __half* Bb = g_xBCh + (size_t)(row0 + j0) * CONVDIM + D_INNER;
    #pragma unroll
    for (int j = 0; j < 4; j++) {
        int c = tid + 256 * j;
        int row = c >> 3;
        uint32_t cc = (uint32_t)(c & 7) * 16;
        uint32_t off = (uint32_t)row * 128 + (cc ^ (((uint32_t)row & 7) << 4));
        CP_ASYNC16(as_base + off, Cb + (size_t)row * CONVDIM + (cc >> 1));
        CP_ASYNC16(bs_base + off, Bb + (size_t)row * CONVDIM + (cc >> 1));
    }
    CP_COMMIT();
    CP_WAIT(0);
    __syncthreads();

    int wm = (wid & 3) * 32;
    int wn = (wid >> 2) * 64;
    int a_row = wm + (lane & 15);
    uint32_t a_kb = (uint32_t)(lane >> 4) * 16;
    int b_row = wn + (lane & 7) + ((lane & 16) ? 8 : 0);
    uint32_t b_kb = (lane & 8) ? 16u : 0u;

    float acc[2][8][4];
    #pragma unroll
    for (int mt = 0; mt < 2; mt++)
        #pragma unroll
        for (int nt = 0; nt < 8; nt++)
            #pragma unroll
            for (int q = 0; q < 4; q++) acc[mt][nt][q] = 0.f;

    #pragma unroll
    for (int ks = 0; ks < 4; ks++) {
        uint32_t afr[2][4];
        #pragma unroll
        for (int mt = 0; mt < 2; mt++) {
            uint32_t row = (uint32_t)(a_row + mt * 16);
            uint32_t c = (uint32_t)ks * 32 + a_kb;
            ldsm_x4(afr[mt], as_base + row * 128 + (c ^ ((row & 7) << 4)));
        }
        uint32_t bfr[4][4];
        #pragma unroll
        for (int nh = 0; nh < 4; nh++) {
            uint32_t row = (uint32_t)(b_row + nh * 16);
            uint32_t c = (uint32_t)ks * 32 + b_kb;
            ldsm_x4(bfr[nh], bs_base + row * 128 + (c ^ ((row & 7) << 4)));
        }
        #pragma unroll
        for (int mt = 0; mt < 2; mt++)
            #pragma unroll
            for (int nt = 0; nt < 8; nt++)
                mma_fp16(acc[mt][nt], afr[mt], &bfr[nt >> 1][(nt & 1) * 2]);
    }

    int g = lane >> 2, tg = lane & 3;
    #pragma unroll
    for (int mt = 0; mt < 2; mt++) {
        int irow = i0 + wm + mt * 16 + g;
        #pragma unroll
        for (int nt = 0; nt < 8; nt++) {
            int col = j0 + wn + nt * 8 + tg * 2;
            *(uint32_t*)(g_Sh + ((size_t)bc * CHUNK + irow) * CHUNK + col) =
                pack2(acc[mt][nt][0], acc[mt][nt][1]);
            *(uint32_t*)(g_Sh + ((size_t)bc * CHUNK + irow + 8) * CHUNK + col) =
                pack2(acc[mt][nt][2], acc[mt][nt][3]);
        }
    }
}

// ============ K7 (fp16 MMA): states[p][n] = sum_t (x[t][p]*w_t) * B[t][n] ============
__global__ __launch_bounds__(256, 2) void k_states_h() {
    __shared__ __align__(16) __half As[128 * 64];
    __shared__ __align__(16) __half Bs[64 * 64];
    __shared__ float wsh[256];
    int bc = blockIdx.x, h = blockIdx.y;
    int row0 = bc * CHUNK;
    int cb = (bc * NHEADS + h) * CHUNK;
    int tid = threadIdx.x, lane = tid & 31, wid = tid >> 5;

    float cum_last = g_cum[cb + 255];
    wsh[tid] = g_dt[(size_t)(row0 + tid) * NHEADS + h] *
               __expf(cum_last - g_cum[cb + tid]);

    uint32_t as_base = smem_u32(As);
    uint32_t bs_base = smem_u32(Bs);

    int wm = (wid & 3) * 32;
    int wn = (wid >> 2) * 32;
    int a_row = wm + (lane & 15);
    uint32_t a_kb = (uint32_t)(lane >> 4) * 16;
    int b_row = wn + (lane & 7) + ((lane & 16) ? 8 : 0);
    uint32_t b_kb = (lane & 8) ? 16u : 0u;

    float acc[2][4][4];
    #pragma unroll
    for (int mt = 0; mt < 2; mt++)
        #pragma unroll
        for (int nt = 0; nt < 4; nt++)
            #pragma unroll
            for (int q = 0; q < 4; q++) acc[mt][nt][q] = 0.f;

    for (int kt = 0; kt < 4; kt++) {
        int t0 = kt * 64;
        __syncthreads();
        #pragma unroll
        for (int jp = 0; jp < 4; jp++) {
            int pair = wid + 8 * jp;
            int t = t0 + 2 * pair;
            const __half* x0 = g_xBCh + (size_t)(row0 + t) * CONVDIM + h * HEADDIM;
            const __half* x1 = x0 + CONVDIM;
            float w0 = wsh[t], w1 = wsh[t + 1];
            #pragma unroll
            for (int r = 0; r < 4; r++) {
                int p = lane + 32 * r;
                uint32_t cbyte = (uint32_t)pair * 4;
                uint32_t off = (uint32_t)p * 128 + (cbyte ^ (((uint32_t)p & 7) << 4));
                *(uint32_t*)((char*)As + off) =
                    pack2(__half2float(x0[p]) * w0, __half2float(x1[p]) * w1);
            }
        }
        #pragma unroll
        for (int q = 0; q < 8; q++) {
            int idx = tid + 256 * q;
            int n = idx >> 5, pair = idx & 31;
            int t = t0 + 2 * pair;
            const __half* b0 = g_xBCh + (size_t)(row0 + t) * CONVDIM + D_INNER;
            uint32_t cbyte = (uint32_t)pair * 4;
            uint32_t off = (uint32_t)n * 128 + (cbyte ^ (((uint32_t)n & 7) << 4));
            *(uint32_t*)((char*)Bs + off) = pack2h(b0[n], b0[CONVDIM + n]);
        }
        __syncthreads();
        #pragma unroll
        for (int ks = 0; ks < 4; ks++) {
            uint32_t afr[2][4];
            #pragma unroll
            for (int mt = 0; mt < 2; mt++) {
                uint32_t row = (uint32_t)(a_row + mt * 16);
                uint32_t c = (uint32_t)ks * 32 + a_kb;
                ldsm_x4(afr[mt], as_base + row * 128 + (c ^ ((row & 7) << 4)));
            }
            uint32_t bfr[2][4];
            #pragma unroll
            for (int nh = 0; nh < 2; nh++) {
                uint32_t row = (uint32_t)(b_row + nh * 16);
                uint32_t c = (uint32_t)ks * 32 + b_kb;
                ldsm_x4(bfr[nh], bs_base + row * 128 + (c ^ ((row & 7) << 4)));
            }
            #pragma unroll
            for (int mt = 0; mt < 2; mt++)
                #pragma unroll
                for (int nt = 0; nt < 4; nt++)
                    mma_fp16(acc[mt][nt], afr[mt], &bfr[nt >> 1][(nt & 1) * 2]);
        }
    }

    size_t base = (size_t)(bc * NHEADS + h) * HEADDIM * D_STATE;
    int g = lane >> 2, tg = lane & 3;
    #pragma unroll
    for (int mt = 0; mt < 2; mt++) {
        int prow = wm + mt * 16 + g;
        #pragma unroll
        for (int nt = 0; nt < 4; nt++) {
            int col = wn + nt * 8 + tg * 2;
            *(float2*)(g_st + base + (size_t)prow * D_STATE + col) =
                make_float2(acc[mt][nt][0], acc[mt][nt][1]);
            *(float2*)(g_st + base + (size_t)(prow + 8) * D_STATE + col) =
                make_float2(acc[mt][nt][2], acc[mt][nt][3]);
        }
    }
}

// ============ fused SSD y-kernel (fp16 fragments, fp32 accumulate, fp16 y out) ============
__global__ __launch_bounds__(256, 2) void k_yfused() {
    __shared__ __align__(16) __half As[128 * 64];
    __shared__ __align__(16) __half Bs[128 * 64];
    __shared__ float gj_all[256];
    __shared__ float cas[8];
    int bc = blockIdx.x, h = blockIdx.y, ih = blockIdx.z;
    int i_base = ih * 128;
    int row0 = bc * CHUNK;
    int cb = (bc * NHEADS + h) * CHUNK;
    size_t psb = (size_t)(bc * NHEADS + h) * HEADDIM * D_STATE;

    int tid = threadIdx.x, lane = tid & 31, wid = tid >> 5;
    int wm = (wid & 3) * 32;
    int wn = (wid >> 2) * 64;

    int si = tid >> 1;
    int sj = (tid & 1) * 32;
    int gi = i_base + si;
    float ci = g_cum[cb + gi];
    float ei = __expf(ci);

    uint32_t as_base = smem_u32(As);
    uint32_t bs_base = smem_u32(Bs);

    int a_row = wm + (lane & 15);
    uint32_t a_kb = (uint32_t)(lane >> 4) * 16;
    int b_row = wn + (lane & 7) + ((lane & 16) ? 8 : 0);
    uint32_t b_kb = (lane & 8) ? 16u : 0u;

    int natt64 = (ih + 1) * 2;
    int nattj = natt64 * 64;

    if (tid < nattj) {
        int j = tid;
        float ca = g_cum[cb + (j & ~31) + 31];
        gj_all[j] = __expf(ca - g_cum[cb + j]) *
                    g_dt[(size_t)(row0 + j) * NHEADS + h];
    }
    if (tid < natt64 * 2) cas[tid] = g_cum[cb + tid * 32 + 31];

    float acc[2][8][4];
    #pragma unroll
    for (int mt = 0; mt < 2; mt++)
        #pragma unroll
        for (int nt = 0; nt < 8; nt++)
            #pragma unroll
            for (int q = 0; q < 4; q++) acc[mt][nt][q] = 0.f;

    int ntiles = natt64 + 1;
    for (int kt = 0; kt < ntiles; kt++) {
        __syncthreads();
        if (kt < natt64) {
            int j0 = kt * 64;
            int jb = j0 + sj;
            if (gi >= jb + 31) {
                float fi = __expf(ci - cas[jb >> 5]);
                const __half* Srow = g_Sh + ((size_t)bc * CHUNK + gi) * CHUNK + jb;
                const float* gjp = gj_all + jb;
                #pragma unroll
                for (int q = 0; q < 4; q++) {
                    uint4 sv = *(const uint4*)(Srow + q * 8);
                    float2 f0 = __half22float2(*(__half2*)&sv.x);
                    float2 f1 = __half22float2(*(__half2*)&sv.y);
                    float2 f2 = __half22float2(*(__half2*)&sv.z);
                    float2 f3 = __half22float2(*(__half2*)&sv.w);
                    uint4 u;
                    u.x = pack2(f0.x * fi * gjp[q*8+0], f0.y * fi * gjp[q*8+1]);
                    u.y = pack2(f1.x * fi * gjp[q*8+2], f1.y * fi * gjp[q*8+3]);
                    u.z = pack2(f2.x * fi * gjp[q*8+4], f2.y * fi * gjp[q*8+5]);
                    u.w = pack2(f3.x * fi * gjp[q*8+6], f3.y * fi * gjp[q*8+7]);
                    uint32_t cbyte = (uint32_t)(sj * 2 + q * 16);
                    uint32_t off = (uint32_t)si * 128 + (cbyte ^ (((uint32_t)si & 7) << 4));
                    *(uint4*)((char*)As + off) = u;
                }
            } else if (gi >= jb) {
                #pragma unroll
                for (int q = 0; q < 4; q++) {
                    float v[8];
                    #pragma unroll
                    for (int r = 0; r < 8; r++) {
                        int j = jb + q * 8 + r;
                        float a = 0.f;
                        if (j <= gi)
                            a = __half2float(g_Sh[((size_t)bc * CHUNK + gi) * CHUNK + j]) *
                                __expf(ci - g_cum[cb + j]) *
                                g_dt[(size_t)(row0 + j) * NHEADS + h];
                        v[r] = a;
                    }
                    uint4 u;
                    u.x = pack2(v[0], v[1]); u.y = pack2(v[2], v[3]);
                    u.z = pack2(v[4], v[5]); u.w = pack2(v[6], v[7]);
                    uint32_t cbyte = (uint32_t)(sj * 2 + q * 16);
                    uint32_t off = (uint32_t)si * 128 + (cbyte ^ (((uint32_t)si & 7) << 4));
                    *(uint4*)((char*)As + off) = u;
                }
            } else {
                #pragma unroll
                for (int q = 0; q < 4; q++) {
                    uint32_t cbyte = (uint32_t)(sj * 2 + q * 16);
                    uint32_t off = (uint32_t)si * 128 + (cbyte ^ (((uint32_t)si & 7) << 4));
                    *(uint4*)((char*)As + off) = make_uint4(0, 0, 0, 0);
                }
            }
            #pragma unroll
            for (int jp = 0; jp < 4; jp++) {
                int pair = wid + 8 * jp;
                int j = j0 + 2 * pair;
                const __half* x0 = g_xBCh + (size_t)(row0 + j) * CONVDIM + h * HEADDIM;
                const __half* x1 = x0 + CONVDIM;
                #pragma unroll
                for (int r = 0; r < 4; r++) {
                    int p = lane + 32 * r;
                    uint32_t cbyte = (uint32_t)pair * 4;
                    uint32_t off = (uint32_t)p * 128 + (cbyte ^ (((uint32_t)p & 7) << 4));
                    *(uint32_t*)((char*)Bs + off) = pack2h(x0[p], x1[p]);
                }
            }
        } else {
            const __half2* crow = (const __half2*)(g_xBCh + (size_t)(row0 + gi) * CONVDIM
                                                   + D_INNER + D_STATE + sj);
            #pragma unroll
            for (int q = 0; q < 4; q++) {
                uint4 hv = *(const uint4*)(crow + q * 4);
                float2 f0 = __half22float2(*(__half2*)&hv.x);
                float2 f1 = __half22float2(*(__half2*)&hv.y);
                float2 f2 = __half22float2(*(__half2*)&hv.z);
                float2 f3 = __half22float2(*(__half2*)&hv.w);
                uint4 u;
                u.x = pack2(f0.x * ei, f0.y * ei);
                u.y = pack2(f1.x * ei, f1.y * ei);
                u.z = pack2(f2.x * ei, f2.y * ei);
                u.w = pack2(f3.x * ei, f3.y * ei);
                uint32_t cbyte = (uint32_t)(sj * 2 + q * 16);
                uint32_t off = (uint32_t)si * 128 + (cbyte ^ (((uint32_t)si & 7) << 4));
                *(uint4*)((char*)As + off) = u;
            }
            int pr = tid >> 1;
            int nc = (tid & 1) * 32;
            const __half* prow = g_psh + psb + (size_t)pr * D_STATE + nc;
            #pragma unroll
            for (int q = 0; q < 2; q++) {
                uint4 u = *(const uint4*)(prow + q * 16);
                uint32_t off = (uint32_t)pr * 128 +
                    (((uint32_t)(nc * 2 + q * 32)) ^ (((uint32_t)pr & 7) << 4));
                *(uint4*)((char*)Bs + off) = u;
                uint4 u2 = *(const uint4*)(prow + q * 16 + 8);
                uint32_t off2 = (uint32_t)pr * 128 +
                    (((uint32_t)(nc * 2 + q * 32 + 16)) ^ (((uint32_t)pr & 7) << 4));
                *(uint4*)((char*)Bs + off2) = u2;
            }
        }
        __syncthreads();
        #pragma unroll
        for (int ks = 0; ks < 4; ks++) {
            uint32_t afr[2][4];
            #pragma unroll
            for (int mt = 0; mt < 2; mt++) {
                uint32_t row = (uint32_t)(a_row + mt * 16);
                uint32_t c = (uint32_t)ks * 32 + a_kb;
                ldsm_x4(afr[mt], as_base + row * 128 + (c ^ ((row & 7) << 4)));
            }
            uint32_t bfr[4][4];
            #pragma unroll
            for (int nh = 0; nh < 4; nh++) {
                uint32_t row = (uint32_t)(b_row + nh * 16);
                uint32_t c = (uint32_t)ks * 32 + b_kb;
                ldsm_x4(bfr[nh], bs_base + row * 128 + (c ^ ((row & 7) << 4)));
            }
            #pragma unroll
            for (int mt = 0; mt < 2; mt++)
                #pragma unroll
                for (int nt = 0; nt < 8; nt++)
                    mma_fp16(acc[mt][nt], afr[mt], &bfr[nt >> 1][(nt & 1) * 2]);
        }
    }

    int g = lane >> 2, tg = lane & 3;
    #pragma unroll
    for (int mt = 0; mt < 2; mt++) {
        int orow = row0 + i_base + wm + mt * 16 + g;
        #pragma unroll
        for (int nt = 0; nt < 8; nt++) {
            int col = h * HEADDIM + wn + nt * 8 + tg * 2;
            *(uint32_t*)(g_yh + (size_t)orow * D_INNER + col) =
                pack2(acc[mt][nt][0], acc[mt][nt][1]);
            *(uint32_t*)(g_yh + (size_t)(orow + 8) * D_INNER + col) =
                pack2(acc[mt][nt][2], acc[mt][nt][3]);
        }
    }
}

// ---------------- reductions ----------------
__device__ __forceinline__ float blockReduceSum256(float v) {
    __shared__ float red[8];
    __shared__ float tot;
    int lane = threadIdx.x & 31, wid = threadIdx.x >> 5;
    #pragma unroll
    for (int o = 16; o; o >>= 1) v += __shfl_down_sync(0xffffffffu, v, o);
    if (lane == 0) red[wid] = v;
    __syncthreads();
    if (wid == 0) {
        float w = (lane < 8) ? red[lane] : 0.f;
        #pragma unroll
        for (int o = 4; o; o >>= 1) w += __shfl_down_sync(0xffffffffu, w, o);
        if (lane == 0) tot = w;
    }
    __syncthreads();
    return tot;
}

// ---------------- K1: l2-normalize weight rows ----------------
__global__ __launch_bounds__(256) void k_normw(const float* __restrict__ W,
                                               __half* __restrict__ Wo, int K, float extra) {
    int r = blockIdx.x;
    const float* wr = W + (size_t)r * K;
    float s2 = 0.f;
    for (int i = threadIdx.x; i < K; i += 256) { float v = wr[i]; s2 += v * v; }
    float totv = blockReduceSum256(s2);
    float sc = extra / fmaxf(sqrtf(totv), 1e-6f);
    for (int i = threadIdx.x; i < K; i += 256)
        Wo[(size_t)r * K + i] = __float2half_rn(wr[i] * sc);
}

// ---------------- K2: layernorm ----------------
__global__ __launch_bounds__(256) void k_layernorm(const float* __restrict__ u,
                                                   const float* __restrict__ w,
                                                   const float* __restrict__ b) {
    int row = blockIdx.x;
    const float* ur = u + (size_t)row * XDIM;
    float v[4]; float s = 0.f, s2 = 0.f;
    #pragma unroll
    for (int k = 0; k < 4; k++) {
        v[k] = ur[threadIdx.x + 256 * k];
        s += v[k]; s2 += v[k] * v[k];
    }
    float sum = blockReduceSum256(s);
    float sumsq = blockReduceSum256(s2);
    float mu = sum * (1.f / XDIM);
    float var = sumsq * (1.f / XDIM) - mu * mu;
    float inv = rsqrtf(var + 1e-5f);
    #pragma unroll
    for (int k = 0; k < 4; k++) {
        int d = threadIdx.x + 256 * k;
        g_lnh[(size_t)row * XDIM + d] = __float2half_rn((v[k] - mu) * inv * w[d] + b[d]);
    }
}

// ---------------- K4: depthwise causal conv + bias + silu (half2, 2 ch/thread) ----------------
__global__ __launch_bounds__(128) void k_conv(const float* __restrict__ cw,
                                              const float* __restrict__ cb) {
    int pairi = blockIdx.x * 128 + threadIdx.x;       // channel pair index
    if (pairi >= CONVDIM / 2) return;
    int ch = pairi * 2;
    int row0 = blockIdx.y * 8;
    int l0 = row0 & (SEQLEN - 1);
    float w00 = cw[ch * 4 + 0], w01 = cw[ch * 4 + 1], w02 = cw[ch * 4 + 2], w03 = cw[ch * 4 + 3];
    float w10 = cw[ch * 4 + 4], w11 = cw[ch * 4 + 5], w12 = cw[ch * 4 + 6], w13 = cw[ch * 4 + 7];
    float b0 = cb[ch], b1 = cb[ch + 1];
    float2 v[11];
    #pragma unroll
    for (int k = 0; k < 11; k++) {
        int l = l0 - 3 + k;
        if (l >= 0) {
            __half2 hv = *(const __half2*)(g_zxh + (size_t)(row0 - 3 + k) * DPROJP + D_INNER + ch);
            v[k] = __half22float2(hv);
        } else {
            v[k] = make_float2(0.f, 0.f);
        }
    }
    #pragma unroll
    for (int r = 0; r < 8; r++) {
        float a0 = b0 + w00 * v[r].x + w01 * v[r + 1].x + w02 * v[r + 2].x + w03 * v[r + 3].x;
        float a1 = b1 + w10 * v[r].y + w11 * v[r + 1].y + w12 * v[r + 2].y + w13 * v[r + 3].y;
        float s0 = a0 / (1.f + __expf(-a0));
        float s1 = a1 / (1.f + __expf(-a1));
        *(uint32_t*)(g_xBCh + (size_t)(row0 + r) * CONVDIM + ch) = pack2(s0, s1);
    }
}

// ---------------- K5: dt softplus + per-chunk cumulative dA ----------------
__global__ __launch_bounds__(256) void k_dtcum(const float* __restrict__ dt_bias,
                                               const float* __restrict__ A_log) {
    int bch = blockIdx.x;
    int h = bch & 15, bc = bch >> 4;
    int t = threadIdx.x;
    int row = bc * CHUNK + t;
    float x = g_dtraw[(size_t)row * NHEADS + h] + dt_bias[h];
    float dtv = (x > 20.f) ? x : log1pf(expf(x));
    g_dt[(size_t)row * NHEADS + h] = dtv;
    float dA = dtv * (-expf(A_log[h]));
    __shared__ float s[256];
    s[t] = dA;
    __syncthreads();
    #pragma unroll
    for (int off = 1; off < 256; off <<= 1) {
        float pv = (t >= off) ? s[t - off] : 0.f;
        __syncthreads();
        s[t] += pv;
        __syncthreads();
    }
    g_cum[(size_t)bch * CHUNK + t] = s[t];
    if (t == 255) g_cdec[bch] = __expf(s[255]);
}

// ---------------- K8: inter-chunk scan (fp32 carry, fp16 ps out) ----------------
__global__ __launch_bounds__(256) void k_scan() {
    int b = blockIdx.x, h = blockIdx.y, z = blockIdx.z;
    int tid = threadIdx.x;
    int e0 = z * 1024 + tid * 4;
    float4 carry = make_float4(0.f, 0.f, 0.f, 0.f);
    for (int c = 0; c < NCPB; c++) {
        int bch = (b * NCPB + c) * NHEADS + h;
        float dec = g_cdec[bch];
        size_t base = (size_t)bch * HEADDIM * D_STATE + e0;
        uint2 pk;
        pk.x = pack2(carry.x, carry.y);
        pk.y = pack2(carry.z, carry.w);
        *(uint2*)(g_psh + base) = pk;
        float4 st = *(const float4*)(g_st + base);
        carry.x = carry.x * dec + st.x;
        carry.y = carry.y * dec + st.y;
        carry.z = carry.z * dec + st.z;
        carry.w = carry.w * dec + st.w;
    }
}

// ---------------- K10: y += D*x, gate, RMS norm (half2 vectorized) ----------------
__global__ __launch_bounds__(256) void k_gate(const float* __restrict__ Dp,
                                              const float* __restrict__ rms_w) {
    int row = blockIdx.x;
    int tid = threadIdx.x;
    float2 gg[4];
    float s2 = 0.f;
    #pragma unroll
    for (int k = 0; k < 4; k++) {
        int idx2 = tid + 256 * k;          // half2 index
        int d = idx2 * 2;
        float2 xv = __half22float2(*(const __half2*)(g_xBCh + (size_t)row * CONVDIM + d));
        float2 yv = __half22float2(*(const __half2*)(g_yh + (size_t)row * D_INNER + d));
        float2 zv = __half22float2(*(const __half2*)(g_zxh + (size_t)row * DPROJP + d));
        float dpv = Dp[d >> 7];
        float v0 = yv.x + dpv * xv.x;
        float v1 = yv.y + dpv * xv.y;
        float sil0 = zv.x / (1.f + __expf(-zv.x));
        float sil1 = zv.y / (1.f + __expf(-zv.y));
        float g0 = v0 * sil0, g1 = v1 * sil1;
        gg[k] = make_float2(g0, g1);
        s2 += g0 * g0 + g1 * g1;
    }
    float tot = blockReduceSum256(s2);
    float sc = rsqrtf(tot * (1.f / D_INNER) + 1e-5f);
    #pragma unroll
    for (int k = 0; k < 4; k++) {
        int idx2 = tid + 256 * k;
        int d = idx2 * 2;
        float2 rw = *(const float2*)(rms_w + d);
        *(uint32_t*)(g_gh + (size_t)row * D_INNER + d) =
            pack2(gg[k].x * sc * rw.x, gg[k].y * sc * rw.y);
    }
}

// ---------------- host launcher ----------------
extern "C" void kernel_launch(void* const* d_in, const int* in_sizes, int n_in,
                              void* d_out, int out_size) {
    const float* u          = (const float*)d_in[0];
    const float* in_proj_w  = (const float*)d_in[1];
    const float* conv_w     = (const float*)d_in[2];
    const float* conv_b     = (const float*)d_in[3];
    const float* dt_bias    = (const float*)d_in[4];
    const float* A_log      = (const float*)d_in[5];
    const float* Dp         = (const float*)d_in[6];
    const float* xnw        = (const float*)d_in[7];
    const float* xnb        = (const float*)d_in[8];
    const float* rms_w      = (const float*)d_in[9];
    const float* out_proj_w = (const float*)d_in[10];
    float* out = (float*)d_out;

    __half *pWinH, *pWoutH, *pLnH, *pGH, *pZxH;
    cudaGetSymbolAddress((void**)&pWinH,  g_Winh);
    cudaGetSymbolAddress((void**)&pWoutH, g_Wouth);
    cudaGetSymbolAddress((void**)&pLnH,   g_lnh);
    cudaGetSymbolAddress((void**)&pGH,    g_gh);
    cudaGetSymbolAddress((void**)&pZxH,   g_zxh);

    static int smem_set = 0;
    if (!smem_set) {
        cudaFuncSetAttribute(gemm_hc, cudaFuncAttributeMaxDynamicSharedMemorySize, GEMM_SMEM);
        cudaFuncSetAttribute(gemm_hc_h, cudaFuncAttributeMaxDynamicSharedMemorySize, GEMM_SMEM);
        smem_set = 1;
    }

    k_normw<<<DPROJ, 256>>>(in_proj_w, pWinH, XDIM, 0.03125f);
    k_normw<<<XDIM, 256>>>(out_proj_w, pWoutH, D_INNER, 1.0f);

    k_layernorm<<<R_TOT, 256>>>(u, xnw, xnb);

    gemm_hc_h<<<dim3(DPROJP / GBN, R_TOT / GBM), 128, GEMM_SMEM>>>(pLnH, pWinH, pZxH, XDIM, DPROJP);

    k_conv<<<dim3((CONVDIM / 2 + 127) / 128, R_TOT / 8), 128>>>(conv_w, conv_b);
    k_dtcum<<<NBC * NHEADS, 256>>>(dt_bias, A_log);

    k_scores_h<<<dim3(NBC, 3), 256>>>();
    k_states_h<<<dim3(NBC, NHEADS), 256>>>();
    k_scan<<<dim3(NBATCH, NHEADS, 8), 256>>>();
    k_yfused<<<dim3(NBC, NHEADS, 2), 256>>>();

    k_gate<<<R_TOT, 256>>>(Dp, rms_w);

    gemm_hc<<<dim3(XDIM / GBN, R_TOT / GBM), 128, GEMM_SMEM>>>(pGH, pWoutH, out, D_INNER, XDIM);
}

// round 17
// speedup vs baseline: 1.0475x; 1.0049x over previous
#include <cuda_runtime.h>
#include <cuda_fp16.h>
#include <math.h>
#include <stdint.h>

// ---------------- problem constants ----------------
#define XDIM    1024
#define D_STATE 64
#define HEADDIM 128
#define D_INNER 2048
#define NHEADS  16
#define CONVDIM 2176              // D_INNER + 2*64
#define DPROJ   4240              // 2*2048 + 2*64 + 16
#define DPROJP  4352              // padded to 128-multiple for GEMM tiles
#define DT_BASE 4224              // D_INNER + CONVDIM
#define CHUNK   256
#define NBATCH  2
#define SEQLEN  4096
#define NCPB    16
#define NBC     32
#define R_TOT   8192

// ---------------- device scratch ----------------
__device__ __half g_lnh [(size_t)R_TOT * XDIM];
__device__ __half g_Winh[(size_t)DPROJP * XDIM];     // rows >= DPROJ stay zero (.bss)
__device__ __half g_Wouth[(size_t)XDIM * D_INNER];
__device__ __half g_gh  [(size_t)R_TOT * D_INNER];
__device__ __half g_zxh [(size_t)R_TOT * DPROJP];    // fp16 in_proj output
__device__ __half g_xBCh[(size_t)R_TOT * CONVDIM];   // fp16 conv output
__device__ __half g_yh  [(size_t)R_TOT * D_INNER];   // fp16 y
__device__ __half g_Sh  [(size_t)NBC * CHUNK * CHUNK];  // fp16 scores
__device__ __half g_psh [(size_t)NBC * NHEADS * HEADDIM * D_STATE];  // fp16 prev states
__device__ float g_dtraw[(size_t)R_TOT * NHEADS];    // fp32 dt_raw side-channel
__device__ float g_dt  [(size_t)R_TOT * NHEADS];
__device__ float g_cum [(size_t)NBC * NHEADS * CHUNK];
__device__ float g_cdec[(size_t)NBC * NHEADS];
__device__ float g_st  [(size_t)NBC * NHEADS * HEADDIM * D_STATE];

// ---------------- PTX helpers (baseline PTX only) ----------------
__device__ __forceinline__ uint32_t smem_u32(const void* p) {
    uint32_t a;
    asm("{ .reg .u64 t; cvta.to.shared.u64 t, %1; cvt.u32.u64 %0, t; }" : "=r"(a) : "l"(p));
    return a;
}
__device__ __forceinline__ uint32_t pack2(float a, float b) {
    __half2 h = __floats2half2_rn(a, b);
    return *(uint32_t*)&h;
}
__device__ __forceinline__ uint32_t pack2h(__half a, __half b) {
    __half2 h = __halves2half2(a, b);
    return *(uint32_t*)&h;
}
#define CP_ASYNC16(s, g) \
    asm volatile("cp.async.cg.shared.global [%0], [%1], 16;" :: "r"(s), "l"(g))
#define CP_COMMIT() asm volatile("cp.async.commit_group;" ::: "memory")
#define CP_WAIT(n)  asm volatile("cp.async.wait_group %0;" :: "n"(n) : "memory")

__device__ __forceinline__ void ldsm_x4(uint32_t* r, uint32_t addr) {
    asm volatile("ldmatrix.sync.aligned.m8n8.x4.shared.b16 {%0,%1,%2,%3}, [%4];"
        : "=r"(r[0]), "=r"(r[1]), "=r"(r[2]), "=r"(r[3]) : "r"(addr));
}
__device__ __forceinline__ void mma_fp16(float* d, const uint32_t* a, const uint32_t* b) {
    asm volatile("mma.sync.aligned.m16n8k16.row.col.f32.f16.f16.f32 "
        "{%0,%1,%2,%3},{%4,%5,%6,%7},{%8,%9},{%0,%1,%2,%3};"
        : "+f"(d[0]), "+f"(d[1]), "+f"(d[2]), "+f"(d[3])
        : "r"(a[0]), "r"(a[1]), "r"(a[2]), "r"(a[3]), "r"(b[0]), "r"(b[1]));
}

// ================= fp16 tensor-core GEMM =================
#define GBM 128
#define GBN 128
#define GBK 64
#define GSTG 3
#define TB_A (GBM * GBK * 2)
#define TB_B (GBN * GBK * 2)
#define STAGE_B (TB_A + TB_B)
#define GEMM_SMEM (GSTG * STAGE_B)

__device__ __forceinline__ void gemm_load_tile_h(const __half* Ab, const __half* Bb,
                                                 int K, int t, uint32_t sb, int tid) {
    const __half* Ap = Ab + (size_t)t * GBK;
    const __half* Bp = Bb + (size_t)t * GBK;
    #pragma unroll
    for (int j = 0; j < 8; j++) {
        int c = tid + 128 * j;
        int row = c >> 3;
        uint32_t cc = (uint32_t)(c & 7) * 16;
        uint32_t off = (uint32_t)row * 128 + (cc ^ (((uint32_t)row & 7) << 4));
        CP_ASYNC16(sb + off, Ap + (size_t)row * K + (cc >> 1));
    }
    uint32_t sb2 = sb + TB_A;
    #pragma unroll
    for (int j = 0; j < 8; j++) {
        int c = tid + 128 * j;
        int row = c >> 3;
        uint32_t cc = (uint32_t)(c & 7) * 16;
        uint32_t off = (uint32_t)row * 128 + (cc ^ (((uint32_t)row & 7) << 4));
        CP_ASYNC16(sb2 + off, Bp + (size_t)row * K + (cc >> 1));
    }
    CP_COMMIT();
}

#define GEMM_MAIN(acc, A, B, K)                                                     \
    int T = (K) / GBK;                                                              \
    gemm_load_tile_h(A, B, K, 0, sbase, tid);                                       \
    gemm_load_tile_h(A, B, K, 1, sbase + STAGE_B, tid);                             \
    for (int t = 0; t < T; t++) {                                                   \
        CP_WAIT(1);                                                                 \
        __syncthreads();                                                            \
        if (t + 2 < T)                                                              \
            gemm_load_tile_h(A, B, K, t + 2, sbase + ((t + 2) % GSTG) * STAGE_B, tid); \
        uint32_t sa = sbase + (t % GSTG) * STAGE_B;                                 \
        uint32_t sb = sa + TB_A;                                                    \
        _Pragma("unroll")                                                           \
        for (int ks = 0; ks < 4; ks++) {                                            \
            uint32_t afr[4][4];                                                     \
            _Pragma("unroll")                                                       \
            for (int mt = 0; mt < 4; mt++) {                                        \
                uint32_t row = (uint32_t)(a_row + mt * 16);                         \
                uint32_t c = (uint32_t)ks * 32 + a_kb;                              \
                ldsm_x4(afr[mt], sa + row * 128 + (c ^ ((row & 7) << 4)));          \
            }                                                                       \
            uint32_t bfr[4][4];                                                     \
            _Pragma("unroll")                                                       \
            for (int nh = 0; nh < 4; nh++) {                                        \
                uint32_t row = (uint32_t)(b_row + nh * 16);                         \
                uint32_t c = (uint32_t)ks * 32 + b_kb;                              \
                ldsm_x4(bfr[nh], sb + row * 128 + (c ^ ((row & 7) << 4)));          \
            }                                                                       \
            _Pragma("unroll")                                                       \
            for (int mt = 0; mt < 4; mt++)                                          \
                _Pragma("unroll")                                                   \
                for (int nt = 0; nt < 8; nt++)                                      \
                    mma_fp16(acc[mt][nt], afr[mt], &bfr[nt >> 1][(nt & 1) * 2]);    \
        }                                                                           \
    }

// fp32-output GEMM (out_proj)
__global__ __launch_bounds__(128, 2) void gemm_hc(const __half* __restrict__ A,
                                                  const __half* __restrict__ B,
                                                  float* __restrict__ C,
                                                  int K, int ldc) {
    extern __shared__ char sm[];
    uint32_t sbase = smem_u32(sm);
    int tid = threadIdx.x, lane = tid & 31, wid = tid >> 5;
    int wm = (wid & 1) * 64, wn = (wid >> 1) * 64;
    int m0 = blockIdx.y * GBM, n0 = blockIdx.x * GBN;
    const __half* Ab = A + (size_t)m0 * K;
    const __half* Bb = B + (size_t)n0 * K;
    int a_row = wm + (lane & 15);
    uint32_t a_kb = (uint32_t)(lane >> 4) * 16;
    int b_row = wn + (lane & 7) + ((lane & 16) ? 8 : 0);
    uint32_t b_kb = (lane & 8) ? 16u : 0u;

    float acc[4][8][4];
    #pragma unroll
    for (int mt = 0; mt < 4; mt++)
        #pragma unroll
        for (int nt = 0; nt < 8; nt++)
            #pragma unroll
            for (int q = 0; q < 4; q++) acc[mt][nt][q] = 0.f;

    GEMM_MAIN(acc, Ab, Bb, K)

    int g = lane >> 2, tg = lane & 3;
    #pragma unroll
    for (int mt = 0; mt < 4; mt++) {
        int rowa = m0 + wm + mt * 16 + g;
        #pragma unroll
        for (int nt = 0; nt < 8; nt++) {
            int col = n0 + wn + nt * 8 + tg * 2;
            *(float2*)(C + (size_t)rowa * ldc + col) =
                make_float2(acc[mt][nt][0], acc[mt][nt][1]);
            *(float2*)(C + (size_t)(rowa + 8) * ldc + col) =
                make_float2(acc[mt][nt][2], acc[mt][nt][3]);
        }
    }
}

// fp16-output GEMM (in_proj) with fp32 dt side-channel
__global__ __launch_bounds__(128, 2) void gemm_hc_h(const __half* __restrict__ A,
                                                    const __half* __restrict__ B,
                                                    __half* __restrict__ C,
                                                    int K, int ldc) {
    extern __shared__ char sm[];
    uint32_t sbase = smem_u32(sm);
    int tid = threadIdx.x, lane = tid & 31, wid = tid >> 5;
    int wm = (wid & 1) * 64, wn = (wid >> 1) * 64;
    int m0 = blockIdx.y * GBM, n0 = blockIdx.x * GBN;
    const __half* Ab = A + (size_t)m0 * K;
    const __half* Bb = B + (size_t)n0 * K;
    int a_row = wm + (lane & 15);
    uint32_t a_kb = (uint32_t)(lane >> 4) * 16;
    int b_row = wn + (lane & 7) + ((lane & 16) ? 8 : 0);
    uint32_t b_kb = (lane & 8) ? 16u : 0u;

    float acc[4][8][4];
    #pragma unroll
    for (int mt = 0; mt < 4; mt++)
        #pragma unroll
        for (int nt = 0; nt < 8; nt++)
            #pragma unroll
            for (int q = 0; q < 4; q++) acc[mt][nt][q] = 0.f;

    GEMM_MAIN(acc, Ab, Bb, K)

    int g = lane >> 2, tg = lane & 3;
    bool has_dt = (n0 + GBN) > DT_BASE;   // only the last N-tile carries dt columns
    #pragma unroll
    for (int mt = 0; mt < 4; mt++) {
        int rowa = m0 + wm + mt * 16 + g;
        #pragma unroll
        for (int nt = 0; nt < 8; nt++) {
            int col = n0 + wn + nt * 8 + tg * 2;
            *(uint32_t*)(C + (size_t)rowa * ldc + col) =
                pack2(acc[mt][nt][0], acc[mt][nt][1]);
            *(uint32_t*)(C + (size_t)(rowa + 8) * ldc + col) =
                pack2(acc[mt][nt][2], acc[mt][nt][3]);
            if (has_dt && col >= DT_BASE && col < DPROJ) {
                int d = col - DT_BASE;
                g_dtraw[(size_t)rowa * NHEADS + d]     = acc[mt][nt][0];
                g_dtraw[(size_t)rowa * NHEADS + d + 1] = acc[mt][nt][1];
                g_dtraw[(size_t)(rowa + 8) * NHEADS + d]     = acc[mt][nt][2];
                g_dtraw[(size_t)(rowa + 8) * NHEADS + d + 1] = acc[mt][nt][3];
            }
        }
    }
}

// ============ K6a (fp16 MMA): S tile = C @ B^T, K=64 (fp16 S out) ============
__global__ __launch_bounds__(256, 2) void k_scores_h() {
    __shared__ __align__(16) __half As[128 * 64];
    __shared__ __align__(16) __half Bs[128 * 64];
    int bc = blockIdx.x;
    int tile = blockIdx.y;
    int i0 = (tile != 0) ? 128 : 0;
    int j0 = (tile == 2) ? 128 : 0;
    int row0 = bc * CHUNK;
    int tid = threadIdx.x, lane = tid & 31, wid = tid >> 5;

    uint32_t as_base = smem_u32(As);
    uint32_t bs_base = smem_u32(Bs);
    const __half* Cb = g_xBCh + (size_t)(row0 + i0) * CONVDIM + D_INNER + D_STATE;
    const __half* Bb = g_xBCh + (size_t)(row0 + j0) * CONVDIM + D_INNER;
    #pragma unroll
    for (int j = 0; j < 4; j++) {
        int c = tid + 256 * j;
        int row = c >> 3;
        uint32_t cc = (uint32_t)(c & 7) * 16;
        uint32_t off = (uint32_t)row * 128 + (cc ^ (((uint32_t)row & 7) << 4));
        CP_ASYNC16(as_base + off, Cb + (size_t)row * CONVDIM + (cc >> 1));
        CP_ASYNC16(bs_base + off, Bb + (size_t)row * CONVDIM + (cc >> 1));
    }
    CP_COMMIT();
    CP_WAIT(0);
    __syncthreads();

    int wm = (wid & 3) * 32;
    int wn = (wid >> 2) * 64;
    int a_row = wm + (lane & 15);
    uint32_t a_kb = (uint32_t)(lane >> 4) * 16;
    int b_row = wn + (lane & 7) + ((lane & 16) ? 8 : 0);
    uint32_t b_kb = (lane & 8) ? 16u : 0u;

    float acc[2][8][4];
    #pragma unroll
    for (int mt = 0; mt < 2; mt++)
        #pragma unroll
        for (int nt = 0; nt < 8; nt++)
            #pragma unroll
            for (int q = 0; q < 4; q++) acc[mt][nt][q] = 0.f;

    #pragma unroll
    for (int ks = 0; ks < 4; ks++) {
        uint32_t afr[2][4];
        #pragma unroll
        for (int mt = 0; mt < 2; mt++) {
            uint32_t row = (uint32_t)(a_row + mt * 16);
            uint32_t c = (uint32_t)ks * 32 + a_kb;
            ldsm_x4(afr[mt], as_base + row * 128 + (c ^ ((row & 7) << 4)));
        }
        uint32_t bfr[4][4];
        #pragma unroll
        for (int nh = 0; nh < 4; nh++) {
            uint32_t row = (uint32_t)(b_row + nh * 16);
            uint32_t c = (uint32_t)ks * 32 + b_kb;
            ldsm_x4(bfr[nh], bs_base + row * 128 + (c ^ ((row & 7) << 4)));
        }
        #pragma unroll
        for (int mt = 0; mt < 2; mt++)
            #pragma unroll
            for (int nt = 0; nt < 8; nt++)
                mma_fp16(acc[mt][nt], afr[mt], &bfr[nt >> 1][(nt & 1) * 2]);
    }

    int g = lane >> 2, tg = lane & 3;
    #pragma unroll
    for (int mt = 0; mt < 2; mt++) {
        int irow = i0 + wm + mt * 16 + g;
        #pragma unroll
        for (int nt = 0; nt < 8; nt++) {
            int col = j0 + wn + nt * 8 + tg * 2;
            *(uint32_t*)(g_Sh + ((size_t)bc * CHUNK + irow) * CHUNK + col) =
                pack2(acc[mt][nt][0], acc[mt][nt][1]);
            *(uint32_t*)(g_Sh + ((size_t)bc * CHUNK + irow + 8) * CHUNK + col) =
                pack2(acc[mt][nt][2], acc[mt][nt][3]);
        }
    }
}

// ============ K7 (fp16 MMA): states[p][n] = sum_t (x[t][p]*w_t) * B[t][n] ============
__global__ __launch_bounds__(256, 2) void k_states_h() {
    __shared__ __align__(16) __half As[128 * 64];
    __shared__ __align__(16) __half Bs[64 * 64];
    __shared__ float wsh[256];
    int bc = blockIdx.x, h = blockIdx.y;
    int row0 = bc * CHUNK;
    int cb = (bc * NHEADS + h) * CHUNK;
    int tid = threadIdx.x, lane = tid & 31, wid = tid >> 5;

    float cum_last = g_cum[cb + 255];
    wsh[tid] = g_dt[(size_t)(row0 + tid) * NHEADS + h] *
               __expf(cum_last - g_cum[cb + tid]);

    uint32_t as_base = smem_u32(As);
    uint32_t bs_base = smem_u32(Bs);

    int wm = (wid & 3) * 32;
    int wn = (wid >> 2) * 32;
    int a_row = wm + (lane & 15);
    uint32_t a_kb = (uint32_t)(lane >> 4) * 16;
    int b_row = wn + (lane & 7) + ((lane & 16) ? 8 : 0);
    uint32_t b_kb = (lane & 8) ? 16u : 0u;

    float acc[2][4][4];
    #pragma unroll
    for (int mt = 0; mt < 2; mt++)
        #pragma unroll
        for (int nt = 0; nt < 4; nt++)
            #pragma unroll
            for (int q = 0; q < 4; q++) acc[mt][nt][q] = 0.f;

    for (int kt = 0; kt < 4; kt++) {
        int t0 = kt * 64;
        __syncthreads();
        #pragma unroll
        for (int jp = 0; jp < 4; jp++) {
            int pair = wid + 8 * jp;
            int t = t0 + 2 * pair;
            const __half* x0 = g_xBCh + (size_t)(row0 + t) * CONVDIM + h * HEADDIM;
            const __half* x1 = x0 + CONVDIM;
            float w0 = wsh[t], w1 = wsh[t + 1];
            #pragma unroll
            for (int r = 0; r < 4; r++) {
                int p = lane + 32 * r;
                uint32_t cbyte = (uint32_t)pair * 4;
                uint32_t off = (uint32_t)p * 128 + (cbyte ^ (((uint32_t)p & 7) << 4));
                *(uint32_t*)((char*)As + off) =
                    pack2(__half2float(x0[p]) * w0, __half2float(x1[p]) * w1);
            }
        }
        #pragma unroll
        for (int q = 0; q < 8; q++) {
            int idx = tid + 256 * q;
            int n = idx >> 5, pair = idx & 31;
            int t = t0 + 2 * pair;
            const __half* b0 = g_xBCh + (size_t)(row0 + t) * CONVDIM + D_INNER;
            uint32_t cbyte = (uint32_t)pair * 4;
            uint32_t off = (uint32_t)n * 128 + (cbyte ^ (((uint32_t)n & 7) << 4));
            *(uint32_t*)((char*)Bs + off) = pack2h(b0[n], b0[CONVDIM + n]);
        }
        __syncthreads();
        #pragma unroll
        for (int ks = 0; ks < 4; ks++) {
            uint32_t afr[2][4];
            #pragma unroll
            for (int mt = 0; mt < 2; mt++) {
                uint32_t row = (uint32_t)(a_row + mt * 16);
                uint32_t c = (uint32_t)ks * 32 + a_kb;
                ldsm_x4(afr[mt], as_base + row * 128 + (c ^ ((row & 7) << 4)));
            }
            uint32_t bfr[2][4];
            #pragma unroll
            for (int nh = 0; nh < 2; nh++) {
                uint32_t row = (uint32_t)(b_row + nh * 16);
                uint32_t c = (uint32_t)ks * 32 + b_kb;
                ldsm_x4(bfr[nh], bs_base + row * 128 + (c ^ ((row & 7) << 4)));
            }
            #pragma unroll
            for (int mt = 0; mt < 2; mt++)
                #pragma unroll
                for (int nt = 0; nt < 4; nt++)
                    mma_fp16(acc[mt][nt], afr[mt], &bfr[nt >> 1][(nt & 1) * 2]);
        }
    }

    size_t base = (size_t)(bc * NHEADS + h) * HEADDIM * D_STATE;
    int g = lane >> 2, tg = lane & 3;
    #pragma unroll
    for (int mt = 0; mt < 2; mt++) {
        int prow = wm + mt * 16 + g;
        #pragma unroll
        for (int nt = 0; nt < 4; nt++) {
            int col = wn + nt * 8 + tg * 2;
            *(float2*)(g_st + base + (size_t)prow * D_STATE + col) =
                make_float2(acc[mt][nt][0], acc[mt][nt][1]);
            *(float2*)(g_st + base + (size_t)(prow + 8) * D_STATE + col) =
                make_float2(acc[mt][nt][2], acc[mt][nt][3]);
        }
    }
}

// ============ fused SSD y-kernel (fp16 fragments, fp32 accumulate, fp16 y out) ============
__global__ __launch_bounds__(256, 2) void k_yfused() {
    __shared__ __align__(16) __half As[128 * 64];
    __shared__ __align__(16) __half Bs[128 * 64];
    __shared__ float gj_all[256];
    __shared__ float cas[8];
    int bc = blockIdx.x, h = blockIdx.y, ih = blockIdx.z;
    int i_base = ih * 128;
    int row0 = bc * CHUNK;
    int cb = (bc * NHEADS + h) * CHUNK;
    size_t psb = (size_t)(bc * NHEADS + h) * HEADDIM * D_STATE;

    int tid = threadIdx.x, lane = tid & 31, wid = tid >> 5;
    int wm = (wid & 3) * 32;
    int wn = (wid >> 2) * 64;

    int si = tid >> 1;
    int sj = (tid & 1) * 32;
    int gi = i_base + si;
    float ci = g_cum[cb + gi];
    float ei = __expf(ci);

    uint32_t as_base = smem_u32(As);
    uint32_t bs_base = smem_u32(Bs);

    int a_row = wm + (lane & 15);
    uint32_t a_kb = (uint32_t)(lane >> 4) * 16;
    int b_row = wn + (lane & 7) + ((lane & 16) ? 8 : 0);
    uint32_t b_kb = (lane & 8) ? 16u : 0u;

    int natt64 = (ih + 1) * 2;
    int nattj = natt64 * 64;

    if (tid < nattj) {
        int j = tid;
        float ca = g_cum[cb + (j & ~31) + 31];
        gj_all[j] = __expf(ca - g_cum[cb + j]) *
                    g_dt[(size_t)(row0 + j) * NHEADS + h];
    }
    if (tid < natt64 * 2) cas[tid] = g_cum[cb + tid * 32 + 31];

    float acc[2][8][4];
    #pragma unroll
    for (int mt = 0; mt < 2; mt++)
        #pragma unroll
        for (int nt = 0; nt < 8; nt++)
            #pragma unroll
            for (int q = 0; q < 4; q++) acc[mt][nt][q] = 0.f;

    int ntiles = natt64 + 1;
    for (int kt = 0; kt < ntiles; kt++) {
        __syncthreads();
        if (kt < natt64) {
            int j0 = kt * 64;
            int jb = j0 + sj;
            if (gi >= jb + 31) {
                float fi = __expf(ci - cas[jb >> 5]);
                const __half* Srow = g_Sh + ((size_t)bc * CHUNK + gi) * CHUNK + jb;
                const float* gjp = gj_all + jb;
                #pragma unroll
                for (int q = 0; q < 4; q++) {
                    uint4 sv = *(const uint4*)(Srow + q * 8);
                    float2 f0 = __half22float2(*(__half2*)&sv.x);
                    float2 f1 = __half22float2(*(__half2*)&sv.y);
                    float2 f2 = __half22float2(*(__half2*)&sv.z);
                    float2 f3 = __half22float2(*(__half2*)&sv.w);
                    uint4 u;
                    u.x = pack2(f0.x * fi * gjp[q*8+0], f0.y * fi * gjp[q*8+1]);
                    u.y = pack2(f1.x * fi * gjp[q*8+2], f1.y * fi * gjp[q*8+3]);
                    u.z = pack2(f2.x * fi * gjp[q*8+4], f2.y * fi * gjp[q*8+5]);
                    u.w = pack2(f3.x * fi * gjp[q*8+6], f3.y * fi * gjp[q*8+7]);
                    uint32_t cbyte = (uint32_t)(sj * 2 + q * 16);
                    uint32_t off = (uint32_t)si * 128 + (cbyte ^ (((uint32_t)si & 7) << 4));
                    *(uint4*)((char*)As + off) = u;
                }
            } else if (gi >= jb) {
                #pragma unroll
                for (int q = 0; q < 4; q++) {
                    float v[8];
                    #pragma unroll
                    for (int r = 0; r < 8; r++) {
                        int j = jb + q * 8 + r;
                        float a = 0.f;
                        if (j <= gi)
                            a = __half2float(g_Sh[((size_t)bc * CHUNK + gi) * CHUNK + j]) *
                                __expf(ci - g_cum[cb + j]) *
                                g_dt[(size_t)(row0 + j) * NHEADS + h];
                        v[r] = a;
                    }
                    uint4 u;
                    u.x = pack2(v[0], v[1]); u.y = pack2(v[2], v[3]);
                    u.z = pack2(v[4], v[5]); u.w = pack2(v[6], v[7]);
                    uint32_t cbyte = (uint32_t)(sj * 2 + q * 16);
                    uint32_t off = (uint32_t)si * 128 + (cbyte ^ (((uint32_t)si & 7) << 4));
                    *(uint4*)((char*)As + off) = u;
                }
            } else {
                #pragma unroll
                for (int q = 0; q < 4; q++) {
                    uint32_t cbyte = (uint32_t)(sj * 2 + q * 16);
                    uint32_t off = (uint32_t)si * 128 + (cbyte ^ (((uint32_t)si & 7) << 4));
                    *(uint4*)((char*)As + off) = make_uint4(0, 0, 0, 0);
                }
            }
            #pragma unroll
            for (int jp = 0; jp < 4; jp++) {
                int pair = wid + 8 * jp;
                int j = j0 + 2 * pair;
                const __half* x0 = g_xBCh + (size_t)(row0 + j) * CONVDIM + h * HEADDIM;
                const __half* x1 = x0 + CONVDIM;
                #pragma unroll
                for (int r = 0; r < 4; r++) {
                    int p = lane + 32 * r;
                    uint32_t cbyte = (uint32_t)pair * 4;
                    uint32_t off = (uint32_t)p * 128 + (cbyte ^ (((uint32_t)p & 7) << 4));
                    *(uint32_t*)((char*)Bs + off) = pack2h(x0[p], x1[p]);
                }
            }
        } else {
            const __half2* crow = (const __half2*)(g_xBCh + (size_t)(row0 + gi) * CONVDIM
                                                   + D_INNER + D_STATE + sj);
            #pragma unroll
            for (int q = 0; q < 4; q++) {
                uint4 hv = *(const uint4*)(crow + q * 4);
                float2 f0 = __half22float2(*(__half2*)&hv.x);
                float2 f1 = __half22float2(*(__half2*)&hv.y);
                float2 f2 = __half22float2(*(__half2*)&hv.z);
                float2 f3 = __half22float2(*(__half2*)&hv.w);
                uint4 u;
                u.x = pack2(f0.x * ei, f0.y * ei);
                u.y = pack2(f1.x * ei, f1.y * ei);
                u.z = pack2(f2.x * ei, f2.y * ei);
                u.w = pack2(f3.x * ei, f3.y * ei);
                uint32_t cbyte = (uint32_t)(sj * 2 + q * 16);
                uint32_t off = (uint32_t)si * 128 + (cbyte ^ (((uint32_t)si & 7) << 4));
                *(uint4*)((char*)As + off) = u;
            }
            int pr = tid >> 1;
            int nc = (tid & 1) * 32;
            const __half* prow = g_psh + psb + (size_t)pr * D_STATE + nc;
            #pragma unroll
            for (int q = 0; q < 2; q++) {
                uint4 u = *(const uint4*)(prow + q * 16);
                uint32_t off = (uint32_t)pr * 128 +
                    (((uint32_t)(nc * 2 + q * 32)) ^ (((uint32_t)pr & 7) << 4));
                *(uint4*)((char*)Bs + off) = u;
                uint4 u2 = *(const uint4*)(prow + q * 16 + 8);
                uint32_t off2 = (uint32_t)pr * 128 +
                    (((uint32_t)(nc * 2 + q * 32 + 16)) ^ (((uint32_t)pr & 7) << 4));
                *(uint4*)((char*)Bs + off2) = u2;
            }
        }
        __syncthreads();
        #pragma unroll
        for (int ks = 0; ks < 4; ks++) {
            uint32_t afr[2][4];
            #pragma unroll
            for (int mt = 0; mt < 2; mt++) {
                uint32_t row = (uint32_t)(a_row + mt * 16);
                uint32_t c = (uint32_t)ks * 32 + a_kb;
                ldsm_x4(afr[mt], as_base + row * 128 + (c ^ ((row & 7) << 4)));
            }
            uint32_t bfr[4][4];
            #pragma unroll
            for (int nh = 0; nh < 4; nh++) {
                uint32_t row = (uint32_t)(b_row + nh * 16);
                uint32_t c = (uint32_t)ks * 32 + b_kb;
                ldsm_x4(bfr[nh], bs_base + row * 128 + (c ^ ((row & 7) << 4)));
            }
            #pragma unroll
            for (int mt = 0; mt < 2; mt++)
                #pragma unroll
                for (int nt = 0; nt < 8; nt++)
                    mma_fp16(acc[mt][nt], afr[mt], &bfr[nt >> 1][(nt & 1) * 2]);
        }
    }

    int g = lane >> 2, tg = lane & 3;
    #pragma unroll
    for (int mt = 0; mt < 2; mt++) {
        int orow = row0 + i_base + wm + mt * 16 + g;
        #pragma unroll
        for (int nt = 0; nt < 8; nt++) {
            int col = h * HEADDIM + wn + nt * 8 + tg * 2;
            *(uint32_t*)(g_yh + (size_t)orow * D_INNER + col) =
                pack2(acc[mt][nt][0], acc[mt][nt][1]);
            *(uint32_t*)(g_yh + (size_t)(orow + 8) * D_INNER + col) =
                pack2(acc[mt][nt][2], acc[mt][nt][3]);
        }
    }
}

// ---------------- reductions ----------------
__device__ __forceinline__ float blockReduceSum256(float v) {
    __shared__ float red[8];
    __shared__ float tot;
    int lane = threadIdx.x & 31, wid = threadIdx.x >> 5;
    #pragma unroll
    for (int o = 16; o; o >>= 1) v += __shfl_down_sync(0xffffffffu, v, o);
    if (lane == 0) red[wid] = v;
    __syncthreads();
    if (wid == 0) {
        float w = (lane < 8) ? red[lane] : 0.f;
        #pragma unroll
        for (int o = 4; o; o >>= 1) w += __shfl_down_sync(0xffffffffu, w, o);
        if (lane == 0) tot = w;
    }
    __syncthreads();
    return tot;
}

// ---------------- K1a: l2-normalize in_proj rows (K=1024, single read, float4) ----------------
__global__ __launch_bounds__(256) void k_normw_in(const float* __restrict__ W) {
    int r = blockIdx.x;
    const float4* wr = (const float4*)(W + (size_t)r * XDIM);
    float4 v = wr[threadIdx.x];                     // 256 threads x 4 = 1024
    float s2 = v.x * v.x + v.y * v.y + v.z * v.z + v.w * v.w;
    float totv = blockReduceSum256(s2);
    float sc = 0.03125f / fmaxf(sqrtf(totv), 1e-6f);
    uint2 o;
    o.x = pack2(v.x * sc, v.y * sc);
    o.y = pack2(v.z * sc, v.w * sc);
    *(uint2*)(g_Winh + (size_t)r * XDIM + threadIdx.x * 4) = o;
}

// ---------------- K1b: l2-normalize out_proj rows (K=2048, single read, float4) ----------------
__global__ __launch_bounds__(256) void k_normw_out(const float* __restrict__ W) {
    int r = blockIdx.x;
    const float4* wr = (const float4*)(W + (size_t)r * D_INNER);
    float4 v0 = wr[threadIdx.x];
    float4 v1 = wr[threadIdx.x + 256];
    float s2 = v0.x * v0.x + v0.y * v0.y + v0.z * v0.z + v0.w * v0.w +
               v1.x * v1.x + v1.y * v1.y + v1.z * v1.z + v1.w * v1.w;
    float totv = blockReduceSum256(s2);
    float sc = 1.0f / fmaxf(sqrtf(totv), 1e-6f);
    uint2 o0, o1;
    o0.x = pack2(v0.x * sc, v0.y * sc);
    o0.y = pack2(v0.z * sc, v0.w * sc);
    o1.x = pack2(v1.x * sc, v1.y * sc);
    o1.y = pack2(v1.z * sc, v1.w * sc);
    *(uint2*)(g_Wouth + (size_t)r * D_INNER + threadIdx.x * 4) = o0;
    *(uint2*)(g_Wouth + (size_t)r * D_INNER + (threadIdx.x + 256) * 4) = o1;
}

// ---------------- K2: layernorm (float4 in, half2 out) ----------------
__global__ __launch_bounds__(256) void k_layernorm(const float* __restrict__ u,
                                                   const float* __restrict__ w,
                                                   const float* __restrict__ b) {
    int row = blockIdx.x;
    const float4* ur = (const float4*)(u + (size_t)row * XDIM);
    float4 v = ur[threadIdx.x];                     // 256 x 4 = 1024
    float s = v.x + v.y + v.z + v.w;
    float s2 = v.x * v.x + v.y * v.y + v.z * v.z + v.w * v.w;
    float sum = blockReduceSum256(s);
    float sumsq = blockReduceSum256(s2);
    float mu = sum * (1.f / XDIM);
    float var = sumsq * (1.f / XDIM) - mu * mu;
    float inv = rsqrtf(var + 1e-5f);
    int d = threadIdx.x * 4;
    float4 wv = *(const float4*)(w + d);
    float4 bv = *(const float4*)(b + d);
    uint2 o;
    o.x = pack2((v.x - mu) * inv * wv.x + bv.x, (v.y - mu) * inv * wv.y + bv.y);
    o.y = pack2((v.z - mu) * inv * wv.z + bv.z, (v.w - mu) * inv * wv.w + bv.w);
    *(uint2*)(g_lnh + (size_t)row * XDIM + d) = o;
}

// ---------------- K4: depthwise causal conv + bias + silu (half2, 2 ch/thread) ----------------
__global__ __launch_bounds__(128) void k_conv(const float* __restrict__ cw,
                                              const float* __restrict__ cb) {
    int pairi = blockIdx.x * 128 + threadIdx.x;       // channel pair index
    if (pairi >= CONVDIM / 2) return;
    int ch = pairi * 2;
    int row0 = blockIdx.y * 8;
    int l0 = row0 & (SEQLEN - 1);
    float w00 = cw[ch * 4 + 0], w01 = cw[ch * 4 + 1], w02 = cw[ch * 4 + 2], w03 = cw[ch * 4 + 3];
    float w10 = cw[ch * 4 + 4], w11 = cw[ch * 4 + 5], w12 = cw[ch * 4 + 6], w13 = cw[ch * 4 + 7];
    float b0 = cb[ch], b1 = cb[ch + 1];
    float2 v[11];
    #pragma unroll
    for (int k = 0; k < 11; k++) {
        int l = l0 - 3 + k;
        if (l >= 0) {
            __half2 hv = *(const __half2*)(g_zxh + (size_t)(row0 - 3 + k) * DPROJP + D_INNER + ch);
            v[k] = __half22float2(hv);
        } else {
            v[k] = make_float2(0.f, 0.f);
        }
    }
    #pragma unroll
    for (int r = 0; r < 8; r++) {
        float a0 = b0 + w00 * v[r].x + w01 * v[r + 1].x + w02 * v[r + 2].x + w03 * v[r + 3].x;
        float a1 = b1 + w10 * v[r].y + w11 * v[r + 1].y + w12 * v[r + 2].y + w13 * v[r + 3].y;
        float s0 = a0 / (1.f + __expf(-a0));
        float s1 = a1 / (1.f + __expf(-a1));
        *(uint32_t*)(g_xBCh + (size_t)(row0 + r) * CONVDIM + ch) = pack2(s0, s1);
    }
}

// ---------------- K5: dt softplus + per-chunk cumulative dA ----------------
__global__ __launch_bounds__(256) void k_dtcum(const float* __restrict__ dt_bias,
                                               const float* __restrict__ A_log) {
    int bch = blockIdx.x;
    int h = bch & 15, bc = bch >> 4;
    int t = threadIdx.x;
    int row = bc * CHUNK + t;
    float x = g_dtraw[(size_t)row * NHEADS + h] + dt_bias[h];
    float dtv = (x > 20.f) ? x : log1pf(expf(x));
    g_dt[(size_t)row * NHEADS + h] = dtv;
    float dA = dtv * (-expf(A_log[h]));
    __shared__ float s[256];
    s[t] = dA;
    __syncthreads();
    #pragma unroll
    for (int off = 1; off < 256; off <<= 1) {
        float pv = (t >= off) ? s[t - off] : 0.f;
        __syncthreads();
        s[t] += pv;
        __syncthreads();
    }
    g_cum[(size_t)bch * CHUNK + t] = s[t];
    if (t == 255) g_cdec[bch] = __expf(s[255]);
}

// ---------------- K8: inter-chunk scan (fp32 carry, fp16 ps out) ----------------
__global__ __launch_bounds__(256) void k_scan() {
    int b = blockIdx.x, h = blockIdx.y, z = blockIdx.z;
    int tid = threadIdx.x;
    int e0 = z * 1024 + tid * 4;
    float4 carry = make_float4(0.f, 0.f, 0.f, 0.f);
    for (int c = 0; c < NCPB; c++) {
        int bch = (b * NCPB + c) * NHEADS + h;
        float dec = g_cdec[bch];
        size_t base = (size_t)bch * HEADDIM * D_STATE + e0;
        uint2 pk;
        pk.x = pack2(carry.x, carry.y);
        pk.y = pack2(carry.z, carry.w);
        *(uint2*)(g_psh + base) = pk;
        float4 st = *(const float4*)(g_st + base);
        carry.x = carry.x * dec + st.x;
        carry.y = carry.y * dec + st.y;
        carry.z = carry.z * dec + st.z;
        carry.w = carry.w * dec + st.w;
    }
}

// ---------------- K10: y += D*x, gate, RMS norm (half2 vectorized) ----------------
__global__ __launch_bounds__(256) void k_gate(const float* __restrict__ Dp,
                                              const float* __restrict__ rms_w) {
    int row = blockIdx.x;
    int tid = threadIdx.x;
    float2 gg[4];
    float s2 = 0.f;
    #pragma unroll
    for (int k = 0; k < 4; k++) {
        int idx2 = tid + 256 * k;          // half2 index
        int d = idx2 * 2;
        float2 xv = __half22float2(*(const __half2*)(g_xBCh + (size_t)row * CONVDIM + d));
        float2 yv = __half22float2(*(const __half2*)(g_yh + (size_t)row * D_INNER + d));
        float2 zv = __half22float2(*(const __half2*)(g_zxh + (size_t)row * DPROJP + d));
        float dpv = Dp[d >> 7];
        float v0 = yv.x + dpv * xv.x;
        float v1 = yv.y + dpv * xv.y;
        float sil0 = zv.x / (1.f + __expf(-zv.x));
        float sil1 = zv.y / (1.f + __expf(-zv.y));
        float g0 = v0 * sil0, g1 = v1 * sil1;
        gg[k] = make_float2(g0, g1);
        s2 += g0 * g0 + g1 * g1;
    }
    float tot = blockReduceSum256(s2);
    float sc = rsqrtf(tot * (1.f / D_INNER) + 1e-5f);
    #pragma unroll
    for (int k = 0; k < 4; k++) {
        int idx2 = tid + 256 * k;
        int d = idx2 * 2;
        float2 rw = *(const float2*)(rms_w + d);
        *(uint32_t*)(g_gh + (size_t)row * D_INNER + d) =
            pack2(gg[k].x * sc * rw.x, gg[k].y * sc * rw.y);
    }
}

// ---------------- host launcher ----------------
extern "C" void kernel_launch(void* const* d_in, const int* in_sizes, int n_in,
                              void* d_out, int out_size) {
    const float* u          = (const float*)d_in[0];
    const float* in_proj_w  = (const float*)d_in[1];
    const float* conv_w     = (const float*)d_in[2];
    const float* conv_b     = (const float*)d_in[3];
    const float* dt_bias    = (const float*)d_in[4];
    const float* A_log      = (const float*)d_in[5];
    const float* Dp         = (const float*)d_in[6];
    const float* xnw        = (const float*)d_in[7];
    const float* xnb        = (const float*)d_in[8];
    const float* rms_w      = (const float*)d_in[9];
    const float* out_proj_w = (const float*)d_in[10];
    float* out = (float*)d_out;

    __half *pWinH, *pWoutH, *pLnH, *pGH, *pZxH;
    cudaGetSymbolAddress((void**)&pWinH,  g_Winh);
    cudaGetSymbolAddress((void**)&pWoutH, g_Wouth);
    cudaGetSymbolAddress((void**)&pLnH,   g_lnh);
    cudaGetSymbolAddress((void**)&pGH,    g_gh);
    cudaGetSymbolAddress((void**)&pZxH,   g_zxh);

    static int smem_set = 0;
    if (!smem_set) {
        cudaFuncSetAttribute(gemm_hc, cudaFuncAttributeMaxDynamicSharedMemorySize, GEMM_SMEM);
        cudaFuncSetAttribute(gemm_hc_h, cudaFuncAttributeMaxDynamicSharedMemorySize, GEMM_SMEM);
        smem_set = 1;
    }

    k_normw_in<<<DPROJ, 256>>>(in_proj_w);
    k_normw_out<<<XDIM, 256>>>(out_proj_w);

    k_layernorm<<<R_TOT, 256>>>(u, xnw, xnb);

    gemm_hc_h<<<dim3(DPROJP / GBN, R_TOT / GBM), 128, GEMM_SMEM>>>(pLnH, pWinH, pZxH, XDIM, DPROJP);

    k_conv<<<dim3((CONVDIM / 2 + 127) / 128, R_TOT / 8), 128>>>(conv_w, conv_b);
    k_dtcum<<<NBC * NHEADS, 256>>>(dt_bias, A_log);

    k_scores_h<<<dim3(NBC, 3), 256>>>();
    k_states_h<<<dim3(NBC, NHEADS), 256>>>();
    k_scan<<<dim3(NBATCH, NHEADS, 8), 256>>>();
    k_yfused<<<dim3(NBC, NHEADS, 2), 256>>>();

    k_gate<<<R_TOT, 256>>>(Dp, rms_w);

    gemm_hc<<<dim3(XDIM / GBN, R_TOT / GBM), 128, GEMM_SMEM>>>(pGH, pWoutH, out, D_INNER, XDIM);
}